// round 8
// baseline (speedup 1.0000x reference)
#include <cuda_runtime.h>
#include <math.h>

#define B_ 2
#define T_ 2048
#define C_ 1024
#define H_ 16
#define D_ 64
#define M_ (B_*T_)          // 4096
#define NQKV (3*C_)         // 3072

typedef unsigned int u32;

// Scratch (allocation-free rule: __device__ globals)
__device__ float g_q[(size_t)B_*H_*T_*D_];     // tf32-grid values
__device__ float g_k[(size_t)B_*H_*T_*D_];
__device__ float g_v[(size_t)B_*H_*T_*D_];
__device__ float g_att[(size_t)M_*C_];         // [b][t][h][d], tf32-grid
__device__ float g_xr[(size_t)M_*C_];          // tf32-rounded x
__device__ float g_wq[(size_t)C_*NQKV];        // tf32-rounded w_qkv
__device__ float g_wp[(size_t)C_*C_];          // tf32-rounded w_proj

__device__ __forceinline__ u32 f2tf(float x) {
    u32 r; asm("cvt.rna.tf32.f32 %0, %1;" : "=r"(r) : "f"(x)); return r;
}
__device__ __forceinline__ float f2tff(float x) { return __uint_as_float(f2tf(x)); }

__device__ __forceinline__ void mma_tf32(float c[4], u32 a0, u32 a1, u32 a2, u32 a3,
                                         u32 b0, u32 b1) {
    asm volatile("mma.sync.aligned.m16n8k8.row.col.f32.tf32.tf32.f32 "
                 "{%0,%1,%2,%3}, {%4,%5,%6,%7}, {%8,%9}, {%0,%1,%2,%3};"
                 : "+f"(c[0]), "+f"(c[1]), "+f"(c[2]), "+f"(c[3])
                 : "r"(a0), "r"(a1), "r"(a2), "r"(a3), "r"(b0), "r"(b1));
}
__device__ __forceinline__ void cp16(u32* smem, const void* gmem) {
    u32 s = (u32)__cvta_generic_to_shared(smem);
    asm volatile("cp.async.cg.shared.global [%0], [%1], 16;\n" :: "r"(s), "l"(gmem));
}

// ---------------------------------------------------------------------------
// Prep: round arrays to the tf32 grid.
// ---------------------------------------------------------------------------
__global__ void round_tf32(const float4* __restrict__ s, float4* __restrict__ d, int n4) {
    int i = blockIdx.x * blockDim.x + threadIdx.x;
    if (i < n4) {
        float4 v = s[i];
        float4 r;
        r.x = f2tff(v.x); r.y = f2tff(v.y); r.z = f2tff(v.z); r.w = f2tff(v.w);
        d[i] = r;
    }
}

// ---------------------------------------------------------------------------
// tf32 tensor-core GEMM: 128x128 tile, BK=32, 256 threads (8 warps 2m x 4n),
// 3-stage cp.async ring, ONE __syncthreads per k-tile. 2 CTAs/SM.
// ---------------------------------------------------------------------------
#define AS_STRIDE 36
#define BS_STRIDE 132
#define NIT (C_/32)
#define STG_W (128*AS_STRIDE + 32*BS_STRIDE)          // words per stage: 8832
#define GEMM_SMEM (3 * STG_W * 4)                     // 105984 B

struct GemmFrags { float c[4][4][4]; };   // [mt][nt][frag]

template<int NDIM>
__device__ __forceinline__ void gemm_cp_body(const float* __restrict__ A,
                                             const float* __restrict__ Bw,
                                             u32* smg, int m0, int n0, GemmFrags& F) {
    int tid = threadIdx.x;
    int lane = tid & 31, wid = tid >> 5;
    int warp_m = wid >> 2, warp_n = wid & 3;    // 2 x 4
    int lr = lane >> 2, lc = lane & 3;

    auto issue = [&](int k0, int s) {
        u32* Ab = smg + s * STG_W;
        u32* Bb = Ab + 128 * AS_STRIDE;
        #pragma unroll
        for (int it = 0; it < 4; ++it) {
            int id = it*256 + tid;
            int row = id >> 3, c = (id & 7) * 4;
            cp16(Ab + row*AS_STRIDE + c, A + (size_t)(m0 + row)*C_ + k0 + c);
        }
        #pragma unroll
        for (int it = 0; it < 4; ++it) {
            int id = it*256 + tid;
            int krow = id >> 5, c = (id & 31) * 4;
            cp16(Bb + krow*BS_STRIDE + c, Bw + (size_t)(k0 + krow)*NDIM + n0 + c);
        }
        asm volatile("cp.async.commit_group;\n");
    };

    issue(0, 0);
    issue(32, 1);
    for (int it = 0; it < NIT; ++it) {
        if (it + 1 < NIT) asm volatile("cp.async.wait_group 1;\n");
        else              asm volatile("cp.async.wait_group 0;\n");
        __syncthreads();
        if (it + 2 < NIT) {
            int s2 = it + 2; s2 -= (s2/3)*3;
            issue((it+2)*32, s2);
        }
        int s = it; s -= (s/3)*3;
        u32* Ab = smg + s * STG_W;
        u32* Bb = Ab + 128 * AS_STRIDE;
        #pragma unroll
        for (int kc = 0; kc < 4; ++kc) {
            int kk = kc * 8;
            u32 af[4][4], bf[4][2];
            #pragma unroll
            for (int mt = 0; mt < 4; ++mt) {
                int mr = warp_m*64 + mt*16;
                af[mt][0] = Ab[(mr + lr    )*AS_STRIDE + kk + lc    ];
                af[mt][1] = Ab[(mr + lr + 8)*AS_STRIDE + kk + lc    ];
                af[mt][2] = Ab[(mr + lr    )*AS_STRIDE + kk + lc + 4];
                af[mt][3] = Ab[(mr + lr + 8)*AS_STRIDE + kk + lc + 4];
            }
            #pragma unroll
            for (int nt = 0; nt < 4; ++nt) {
                int nc = warp_n*32 + nt*8;
                bf[nt][0] = Bb[(kk + lc    )*BS_STRIDE + nc + lr];
                bf[nt][1] = Bb[(kk + lc + 4)*BS_STRIDE + nc + lr];
            }
            #pragma unroll
            for (int mt = 0; mt < 4; ++mt)
                #pragma unroll
                for (int nt = 0; nt < 4; ++nt)
                    mma_tf32(F.c[mt][nt], af[mt][0], af[mt][1], af[mt][2], af[mt][3],
                             bf[nt][0], bf[nt][1]);
        }
    }
}

__global__ __launch_bounds__(256, 2) void qkv_gemm() {
    extern __shared__ u32 smg[];
    int tid = threadIdx.x;
    int lane = tid & 31, wid = tid >> 5;
    int warp_m = wid >> 2, warp_n = wid & 3;
    int lr = lane >> 2, lc = lane & 3;
    int m0 = blockIdx.y * 128, n0 = blockIdx.x * 128;

    GemmFrags F = {};
    gemm_cp_body<NQKV>(g_xr, g_wq, smg, m0, n0, F);

    // Epilogue: scatter qkv, rounding to tf32 grid.
    #pragma unroll
    for (int mt = 0; mt < 4; ++mt) {
        #pragma unroll
        for (int nt = 0; nt < 4; ++nt) {
            #pragma unroll
            for (int f = 0; f < 4; ++f) {
                int m = m0 + warp_m*64 + mt*16 + lr + (f >> 1)*8;
                int n = n0 + warp_n*32 + nt*8 + lc*2 + (f & 1);
                int bb = m >> 11, t = m & 2047;
                int three = n % 3;
                int hd = n / 3;
                int h = hd >> 6, d = hd & 63;
                size_t dst = (((size_t)(bb*H_ + h))*T_ + t)*D_ + d;
                float v = f2tff(F.c[mt][nt][f]);
                if (three == 0)      g_q[dst] = v;
                else if (three == 1) g_k[dst] = v;
                else                 g_v[dst] = v;
            }
        }
    }
}

__global__ __launch_bounds__(256, 2) void proj_gemm(const float* __restrict__ bias,
                                                    float* __restrict__ out) {
    extern __shared__ u32 smg[];
    int tid = threadIdx.x;
    int lane = tid & 31, wid = tid >> 5;
    int warp_m = wid >> 2, warp_n = wid & 3;
    int lr = lane >> 2, lc = lane & 3;
    int m0 = blockIdx.y * 128, n0 = blockIdx.x * 128;

    GemmFrags F = {};
    gemm_cp_body<C_>(g_att, g_wp, smg, m0, n0, F);

    #pragma unroll
    for (int mt = 0; mt < 4; ++mt) {
        #pragma unroll
        for (int nt = 0; nt < 4; ++nt) {
            #pragma unroll
            for (int f = 0; f < 4; ++f) {
                int m = m0 + warp_m*64 + mt*16 + lr + (f >> 1)*8;
                int n = n0 + warp_n*32 + nt*8 + lc*2 + (f & 1);
                out[(size_t)m * C_ + n] = F.c[mt][nt][f] + bias[n];
            }
        }
    }
}

// ---------------------------------------------------------------------------
// Flash attention, BQ=128, BK=64, 256 threads = 8 warps as 4(m) x 2(n),
// warp tile 32x32. tf32 mma phases, cp.async double-buffered K/V.
// ---------------------------------------------------------------------------
#define QS 68
#define VSS 72
// word offsets
#define AOFF_K  (128*QS)                 // K[2][64][QS]
#define AOFF_V  (AOFF_K + 2*64*QS)       // V[2][64][VSS]
#define AOFF_S  (AOFF_V + 2*64*VSS)      // S[128][QS]
#define AOFF_M  (AOFF_S + 128*QS)
#define ATTN_SMEM ((AOFF_M + 3*128) * 4) // 142848 B

__global__ __launch_bounds__(256) void attn_kernel() {
    extern __shared__ char smc[];
    u32* Qs = (u32*)smc;
    u32* Kb = Qs + AOFF_K;
    u32* Vb = Qs + AOFF_V;
    float* Ss = (float*)(Qs + AOFF_S);
    u32* Ps = (u32*)Ss;
    float* mrow = (float*)(Qs + AOFF_M);
    float* lrow = mrow + 128;
    float* rrow = lrow + 128;

    int tid = threadIdx.x;
    int lane = tid & 31, wid = tid >> 5;
    int warp_m = wid >> 1, warp_n = wid & 1;   // 4 x 2
    int lr = lane >> 2, lc = lane & 3;
    int mr = warp_m * 32;

    int bh = blockIdx.y;
    int b = bh >> 4, h = bh & 15;
    int qt = gridDim.x - 1 - blockIdx.x;       // heavy CTAs first
    int qBase = qt * 128;

    const float* qg  = g_q + (((size_t)(b*H_ + h))*T_ + qBase)*D_;
    const float* kgb = g_k + ((size_t)(b*H_ + h))*T_*D_;
    const float* vgb = g_v + ((size_t)(b*H_ + h))*T_*D_;

    auto issueKV = [&](int kt, int s) {
        const float* kg = kgb + (size_t)kt*64*D_;
        const float* vg = vgb + (size_t)kt*64*D_;
        u32* Kd = Kb + s*64*QS;
        u32* Vd = Vb + s*64*VSS;
        #pragma unroll
        for (int it = 0; it < 4; ++it) {
            int id = it*256 + tid;
            int row = id >> 4, c = (id & 15) * 4;
            cp16(Kd + row*QS + c, kg + (size_t)row*D_ + c);
            cp16(Vd + row*VSS + c, vg + (size_t)row*D_ + c);
        }
        asm volatile("cp.async.commit_group;\n");
    };

    // group 0: Q (128 rows) + K0 + V0
    #pragma unroll
    for (int it = 0; it < 8; ++it) {
        int id = it*256 + tid;
        int row = id >> 4, c = (id & 15) * 4;
        cp16(Qs + row*QS + c, qg + (size_t)row*D_ + c);
    }
    issueKV(0, 0);
    if (tid < 128) { mrow[tid] = -INFINITY; lrow[tid] = 0.0f; }

    float o[2][4][4] = {};            // [mt][nt][frag]
    const float scale = 0.125f;
    int nkt = 2*qt + 2;

    for (int kt = 0; kt < nkt; ++kt) {
        int s = kt & 1;
        if (kt + 1 < nkt) {
            issueKV(kt+1, s^1);
            asm volatile("cp.async.wait_group 1;\n");
        } else {
            asm volatile("cp.async.wait_group 0;\n");
        }
        __syncthreads();
        u32* Ks = Kb + s*64*QS;
        u32* Vs = Vb + s*64*VSS;
        int kBase = kt * 64;

        // Phase A: S = Q K^T  (warp tile 32x32)
        {
            float sacc[2][4][4] = {};
            #pragma unroll
            for (int kk = 0; kk < 64; kk += 8) {
                u32 af[2][4];
                #pragma unroll
                for (int mt = 0; mt < 2; ++mt) {
                    int rb = mr + mt*16;
                    af[mt][0] = Qs[(rb+lr  )*QS + kk+lc  ];
                    af[mt][1] = Qs[(rb+lr+8)*QS + kk+lc  ];
                    af[mt][2] = Qs[(rb+lr  )*QS + kk+lc+4];
                    af[mt][3] = Qs[(rb+lr+8)*QS + kk+lc+4];
                }
                #pragma unroll
                for (int nt = 0; nt < 4; ++nt) {
                    int nc = warp_n*32 + nt*8;
                    u32 b0 = Ks[(nc+lr)*QS + kk+lc  ];
                    u32 b1 = Ks[(nc+lr)*QS + kk+lc+4];
                    #pragma unroll
                    for (int mt = 0; mt < 2; ++mt)
                        mma_tf32(sacc[mt][nt], af[mt][0], af[mt][1], af[mt][2], af[mt][3],
                                 b0, b1);
                }
            }
            #pragma unroll
            for (int mt = 0; mt < 2; ++mt) {
                #pragma unroll
                for (int nt = 0; nt < 4; ++nt) {
                    int nc = warp_n*32 + nt*8;
                    #pragma unroll
                    for (int f = 0; f < 4; ++f) {
                        int row = mr + mt*16 + lr + (f >> 1)*8;
                        int col = nc + lc*2 + (f & 1);
                        int qi = qBase + row, kj = kBase + col;
                        Ss[row*QS + col] = (kj <= qi) ? sacc[mt][nt][f]*scale : -INFINITY;
                    }
                }
            }
        }
        __syncthreads();

        // Phase B: online softmax; P (tf32) overwrites S in place.
        // 2 threads per row, 32 cols each.
        {
            int row = tid >> 1, g = tid & 1;
            float sv[32];
            float lm = -INFINITY;
            #pragma unroll
            for (int j = 0; j < 32; ++j) {
                sv[j] = Ss[row*QS + g*32 + j];
                lm = fmaxf(lm, sv[j]);
            }
            lm = fmaxf(lm, __shfl_xor_sync(0xffffffffu, lm, 1));
            float newm = fmaxf(mrow[row], lm);
            float ls = 0.0f;
            #pragma unroll
            for (int j = 0; j < 32; ++j) {
                float p = __expf(sv[j] - newm);
                ls += p;
                Ps[row*QS + g*32 + j] = f2tf(p);
            }
            ls += __shfl_xor_sync(0xffffffffu, ls, 1);
            if (g == 0) {
                float r = __expf(mrow[row] - newm);
                rrow[row] = r;
                lrow[row] = lrow[row] * r + ls;
                mrow[row] = newm;
            }
        }
        __syncthreads();

        // Phase C: O = O*r + P V
        {
            #pragma unroll
            for (int mt = 0; mt < 2; ++mt) {
                float r0 = rrow[mr + mt*16 + lr];
                float r1 = rrow[mr + mt*16 + lr + 8];
                #pragma unroll
                for (int nt = 0; nt < 4; ++nt) {
                    o[mt][nt][0] *= r0; o[mt][nt][1] *= r0;
                    o[mt][nt][2] *= r1; o[mt][nt][3] *= r1;
                }
            }
            #pragma unroll
            for (int kk = 0; kk < 64; kk += 8) {
                u32 af[2][4];
                #pragma unroll
                for (int mt = 0; mt < 2; ++mt) {
                    int rb = mr + mt*16;
                    af[mt][0] = Ps[(rb+lr  )*QS + kk+lc  ];
                    af[mt][1] = Ps[(rb+lr+8)*QS + kk+lc  ];
                    af[mt][2] = Ps[(rb+lr  )*QS + kk+lc+4];
                    af[mt][3] = Ps[(rb+lr+8)*QS + kk+lc+4];
                }
                #pragma unroll
                for (int nt = 0; nt < 4; ++nt) {
                    int nc = warp_n*32 + nt*8;
                    u32 b0 = Vs[(kk+lc  )*VSS + nc+lr];
                    u32 b1 = Vs[(kk+lc+4)*VSS + nc+lr];
                    #pragma unroll
                    for (int mt = 0; mt < 2; ++mt)
                        mma_tf32(o[mt][nt], af[mt][0], af[mt][1], af[mt][2], af[mt][3],
                                 b0, b1);
                }
            }
        }
        __syncthreads();   // protect K/V buffer before next iteration's issue
    }

    // Epilogue: normalize, round to tf32 grid, write [b][t][h][d]
    #pragma unroll
    for (int mt = 0; mt < 2; ++mt) {
        #pragma unroll
        for (int half = 0; half < 2; ++half) {
            int row = mr + mt*16 + lr + half*8;
            float inv = 1.0f / lrow[row];
            int t = qBase + row;
            float* og = g_att + (((size_t)(b*T_ + t))*H_ + h)*D_;
            #pragma unroll
            for (int nt = 0; nt < 4; ++nt) {
                int d = warp_n*32 + nt*8 + lc*2;
                float2 w;
                w.x = f2tff(o[mt][nt][half*2+0] * inv);
                w.y = f2tff(o[mt][nt][half*2+1] * inv);
                *(float2*)(og + d) = w;
            }
        }
    }
}

// ---------------------------------------------------------------------------
extern "C" void kernel_launch(void* const* d_in, const int* in_sizes, int n_in,
                              void* d_out, int out_size) {
    const float* x      = (const float*)d_in[0];
    const float* w_qkv  = (const float*)d_in[1];
    const float* w_proj = (const float*)d_in[2];
    const float* b_proj = (const float*)d_in[3];
    float* out = (float*)d_out;

    cudaFuncSetAttribute(attn_kernel,
                         cudaFuncAttributeMaxDynamicSharedMemorySize, ATTN_SMEM);
    cudaFuncSetAttribute(qkv_gemm,
                         cudaFuncAttributeMaxDynamicSharedMemorySize, GEMM_SMEM);
    cudaFuncSetAttribute(proj_gemm,
                         cudaFuncAttributeMaxDynamicSharedMemorySize, GEMM_SMEM);

    float *g_xr_p, *g_wq_p, *g_wp_p;
    cudaGetSymbolAddress((void**)&g_xr_p, g_xr);
    cudaGetSymbolAddress((void**)&g_wq_p, g_wq);
    cudaGetSymbolAddress((void**)&g_wp_p, g_wp);

    int n4x = M_*C_/4, n4q = C_*NQKV/4, n4p = C_*C_/4;
    round_tf32<<<(n4x+255)/256, 256>>>((const float4*)x, (float4*)g_xr_p, n4x);
    round_tf32<<<(n4q+255)/256, 256>>>((const float4*)w_qkv, (float4*)g_wq_p, n4q);
    round_tf32<<<(n4p+255)/256, 256>>>((const float4*)w_proj, (float4*)g_wp_p, n4p);

    qkv_gemm<<<dim3(NQKV/128, M_/128), 256, GEMM_SMEM>>>();
    attn_kernel<<<dim3(T_/128, B_*H_), 256, ATTN_SMEM>>>();
    proj_gemm<<<dim3(C_/128, M_/128), 256, GEMM_SMEM>>>(b_proj, out);
}

// round 9
// speedup vs baseline: 1.5180x; 1.5180x over previous
#include <cuda_runtime.h>
#include <cuda_fp16.h>
#include <math.h>

#define B_ 2
#define T_ 2048
#define C_ 1024
#define H_ 16
#define D_ 64
#define M_ (B_*T_)          // 4096
#define NQKV (3*C_)         // 3072

typedef unsigned int u32;

// Scratch (allocation-free rule: __device__ globals), all fp16
__device__ __align__(16) __half g_qh[(size_t)B_*H_*T_*D_];
__device__ __align__(16) __half g_kh[(size_t)B_*H_*T_*D_];
__device__ __align__(16) __half g_vh[(size_t)B_*H_*T_*D_];
__device__ __align__(16) __half g_atth[(size_t)M_*C_];   // [b][t][h][d] == [M][C]
__device__ __align__(16) __half g_xh[(size_t)M_*C_];     // x as half      [M][K]
__device__ __align__(16) __half g_wqh[(size_t)NQKV*C_];  // w_qkv^T half   [N][K]
__device__ __align__(16) __half g_wph[(size_t)C_*C_];    // w_proj^T half  [N][K]

// ---------------------------------------------------------------------------
// Primitives
// ---------------------------------------------------------------------------
__device__ __forceinline__ void mma_f16(float c[4], u32 a0, u32 a1, u32 a2, u32 a3,
                                        u32 b0, u32 b1) {
    asm volatile("mma.sync.aligned.m16n8k16.row.col.f32.f16.f16.f32 "
                 "{%0,%1,%2,%3}, {%4,%5,%6,%7}, {%8,%9}, {%0,%1,%2,%3};"
                 : "+f"(c[0]), "+f"(c[1]), "+f"(c[2]), "+f"(c[3])
                 : "r"(a0), "r"(a1), "r"(a2), "r"(a3), "r"(b0), "r"(b1));
}
__device__ __forceinline__ void ldsm4(u32& r0, u32& r1, u32& r2, u32& r3, u32 addr) {
    asm volatile("ldmatrix.sync.aligned.m8n8.x4.shared.b16 {%0,%1,%2,%3}, [%4];"
                 : "=r"(r0), "=r"(r1), "=r"(r2), "=r"(r3) : "r"(addr));
}
__device__ __forceinline__ void ldsm4t(u32& r0, u32& r1, u32& r2, u32& r3, u32 addr) {
    asm volatile("ldmatrix.sync.aligned.m8n8.x4.trans.shared.b16 {%0,%1,%2,%3}, [%4];"
                 : "=r"(r0), "=r"(r1), "=r"(r2), "=r"(r3) : "r"(addr));
}
__device__ __forceinline__ void cp16(void* smem, const void* gmem) {
    u32 s = (u32)__cvta_generic_to_shared(smem);
    asm volatile("cp.async.cg.shared.global [%0], [%1], 16;\n" :: "r"(s), "l"(gmem));
}

// ---------------------------------------------------------------------------
// Prep kernels
// ---------------------------------------------------------------------------
__global__ void to_half(const float4* __restrict__ s, __half2* __restrict__ d, int n4) {
    int i = blockIdx.x * blockDim.x + threadIdx.x;
    if (i < n4) {
        float4 v = s[i];
        d[i*2+0] = __floats2half2_rn(v.x, v.y);
        d[i*2+1] = __floats2half2_rn(v.z, v.w);
    }
}
// Wt[n][k] = half(W[k][n]); W is [Kd][Nd] f32
__global__ void transp_half(const float* __restrict__ W, __half* __restrict__ Wt,
                            int Kd, int Nd) {
    __shared__ float t[32][33];
    int bx = blockIdx.x * 32;   // N
    int by = blockIdx.y * 32;   // K
    int tx = threadIdx.x, ty = threadIdx.y;
    #pragma unroll
    for (int i = 0; i < 32; i += 8)
        t[ty+i][tx] = W[(size_t)(by+ty+i)*Nd + bx+tx];
    __syncthreads();
    #pragma unroll
    for (int i = 0; i < 32; i += 8)
        Wt[(size_t)(bx+ty+i)*Kd + by+tx] = __float2half_rn(t[tx][ty+i]);
}

// ---------------------------------------------------------------------------
// fp16 tensor GEMM: 128x128 tile, BK=32, 256 threads (8 warps 2m x 4n),
// 2-stage cp.async, ldmatrix fragments. A and B both [outer][K] half.
// Row stride 40 halfs (80B): 16B-chunk offsets mod 128 distinct -> no conflicts.
// ---------------------------------------------------------------------------
#define ASTR 40
#define TILE_BYTES (128*ASTR*2)            // 10240 per operand
#define STG_B (2*TILE_BYTES)               // 20480 per stage
#define GEMM_SMEM (2*STG_B)                // 40960
#define NIT (C_/32)

struct GemmFrags { float c[4][4][4]; };    // [mt][nt][frag]

__device__ __forceinline__ void gemm_f16_body(const __half* __restrict__ A,
                                              const __half* __restrict__ Bw,
                                              char* smem, int m0, int n0,
                                              GemmFrags& F) {
    int tid = threadIdx.x;
    int lane = tid & 31, wid = tid >> 5;
    int warp_m = wid >> 2, warp_n = wid & 3;    // 2 x 4
    u32 base = (u32)__cvta_generic_to_shared(smem);

    int l8 = lane & 7;
    int arow = l8 + ((lane >> 3) & 1) * 8, ac = (lane >> 4) * 16;      // A/x4 map (bytes for +8 cols)
    int brow = l8 + (lane >> 4) * 8,       bc = ((lane >> 3) & 1) * 16; // B/x4 map

    auto issue = [&](int k0, int s) {
        char* Ab = smem + s*STG_B;
        char* Bb = Ab + TILE_BYTES;
        #pragma unroll
        for (int it = 0; it < 2; ++it) {
            int id = it*256 + tid;
            int row = id >> 2, c = (id & 3) * 8;
            cp16(Ab + row*80 + c*2, A + (size_t)(m0 + row)*C_ + k0 + c);
            cp16(Bb + row*80 + c*2, Bw + (size_t)(n0 + row)*C_ + k0 + c);
        }
        asm volatile("cp.async.commit_group;\n");
    };

    issue(0, 0);
    for (int it = 0; it < NIT; ++it) {
        if (it + 1 < NIT) {
            issue((it+1)*32, (it+1) & 1);
            asm volatile("cp.async.wait_group 1;\n");
        } else {
            asm volatile("cp.async.wait_group 0;\n");
        }
        __syncthreads();
        u32 Ab = base + (it & 1)*STG_B;
        u32 Bb = Ab + TILE_BYTES;
        #pragma unroll
        for (int ks = 0; ks < 2; ++ks) {
            int kb = ks*32;   // bytes: ks*16 halfs
            u32 af[4][4], bf[2][4];
            #pragma unroll
            for (int mt = 0; mt < 4; ++mt)
                ldsm4(af[mt][0], af[mt][1], af[mt][2], af[mt][3],
                      Ab + (warp_m*64 + mt*16 + arow)*80 + kb + ac);
            #pragma unroll
            for (int nt2 = 0; nt2 < 2; ++nt2)
                ldsm4(bf[nt2][0], bf[nt2][1], bf[nt2][2], bf[nt2][3],
                      Bb + (warp_n*32 + nt2*16 + brow)*80 + kb + bc);
            #pragma unroll
            for (int mt = 0; mt < 4; ++mt)
                #pragma unroll
                for (int nt = 0; nt < 4; ++nt)
                    mma_f16(F.c[mt][nt], af[mt][0], af[mt][1], af[mt][2], af[mt][3],
                            bf[nt>>1][(nt&1)*2], bf[nt>>1][(nt&1)*2+1]);
        }
        __syncthreads();
    }
}

__global__ __launch_bounds__(256, 2) void qkv_gemm() {
    extern __shared__ char smg[];
    int tid = threadIdx.x;
    int lane = tid & 31, wid = tid >> 5;
    int warp_m = wid >> 2, warp_n = wid & 3;
    int lr = lane >> 2, lc = lane & 3;
    int m0 = blockIdx.y * 128, n0 = blockIdx.x * 128;

    GemmFrags F = {};
    gemm_f16_body(g_xh, g_wqh, smg, m0, n0, F);

    #pragma unroll
    for (int mt = 0; mt < 4; ++mt) {
        #pragma unroll
        for (int nt = 0; nt < 4; ++nt) {
            #pragma unroll
            for (int f = 0; f < 4; ++f) {
                int m = m0 + warp_m*64 + mt*16 + lr + (f >> 1)*8;
                int n = n0 + warp_n*32 + nt*8 + lc*2 + (f & 1);
                int bb = m >> 11, t = m & 2047;
                int three = n % 3;
                int hd = n / 3;
                int h = hd >> 6, d = hd & 63;
                size_t dst = (((size_t)(bb*H_ + h))*T_ + t)*D_ + d;
                __half v = __float2half_rn(F.c[mt][nt][f]);
                if (three == 0)      g_qh[dst] = v;
                else if (three == 1) g_kh[dst] = v;
                else                 g_vh[dst] = v;
            }
        }
    }
}

__global__ __launch_bounds__(256, 2) void proj_gemm(const float* __restrict__ bias,
                                                    float* __restrict__ out) {
    extern __shared__ char smg[];
    int tid = threadIdx.x;
    int lane = tid & 31, wid = tid >> 5;
    int warp_m = wid >> 2, warp_n = wid & 3;
    int lr = lane >> 2, lc = lane & 3;
    int m0 = blockIdx.y * 128, n0 = blockIdx.x * 128;

    GemmFrags F = {};
    gemm_f16_body(g_atth, g_wph, smg, m0, n0, F);

    #pragma unroll
    for (int mt = 0; mt < 4; ++mt) {
        #pragma unroll
        for (int nt = 0; nt < 4; ++nt) {
            #pragma unroll
            for (int f = 0; f < 4; ++f) {
                int m = m0 + warp_m*64 + mt*16 + lr + (f >> 1)*8;
                int n = n0 + warp_n*32 + nt*8 + lc*2 + (f & 1);
                out[(size_t)m * C_ + n] = F.c[mt][nt][f] + bias[n];
            }
        }
    }
}

// ---------------------------------------------------------------------------
// Flash attention fp16: BQ=64, BK=64, 256 threads = 8 warps (4m x 2n),
// warp tile 16x32. ldmatrix fragments, cp.async double-buffered K/V.
// Half-tile row stride 72 halfs (144B): conflict-free. Softmax fp32.
// ---------------------------------------------------------------------------
#define HST 72                       // halfs
#define SST 68                       // floats
// byte offsets
#define QO  0
#define KO  (QO + 64*HST*2)          // 9216
#define VO  (KO + 2*64*HST*2)        // 27648
#define PO  (VO + 2*64*HST*2)        // 46080
#define SO  (PO + 64*HST*2)          // 55296
#define MO  (SO + 64*SST*4)          // 72704
#define ATTN_SMEM (MO + 3*64*4)      // 73472

__global__ __launch_bounds__(256) void attn_kernel() {
    extern __shared__ char smc[];
    __half* Qs = (__half*)(smc + QO);
    __half* Kb = (__half*)(smc + KO);
    __half* Vb = (__half*)(smc + VO);
    __half* Ps = (__half*)(smc + PO);
    float* Ss  = (float*)(smc + SO);
    float* mrow = (float*)(smc + MO);
    float* lrow = mrow + 64;
    float* rrow = lrow + 64;
    u32 base = (u32)__cvta_generic_to_shared(smc);

    int tid = threadIdx.x;
    int lane = tid & 31, wid = tid >> 5;
    int warp_m = wid >> 1, warp_n = wid & 1;   // 4 x 2
    int lr = lane >> 2, lc = lane & 3;
    int mr = warp_m * 16;
    int nbase = warp_n * 32;

    int l8 = lane & 7;
    int arow = l8 + ((lane >> 3) & 1) * 8, ac = (lane >> 4) * 16;   // A + V-trans map
    int brow = l8 + (lane >> 4) * 8,       bc = ((lane >> 3) & 1) * 16;

    int bh = blockIdx.y;
    int b = bh >> 4, h = bh & 15;
    int qt = gridDim.x - 1 - blockIdx.x;       // heavy CTAs first
    int qBase = qt * 64;

    const __half* qg  = g_qh + (((size_t)(b*H_ + h))*T_ + qBase)*D_;
    const __half* kgb = g_kh + ((size_t)(b*H_ + h))*T_*D_;
    const __half* vgb = g_vh + ((size_t)(b*H_ + h))*T_*D_;

    auto issueKV = [&](int kt, int s) {
        const __half* kg = kgb + (size_t)kt*64*D_;
        const __half* vg = vgb + (size_t)kt*64*D_;
        __half* Kd = Kb + s*64*HST;
        __half* Vd = Vb + s*64*HST;
        #pragma unroll
        for (int it = 0; it < 2; ++it) {
            int id = it*256 + tid;
            int row = id >> 3, c = (id & 7) * 8;
            cp16(Kd + row*HST + c, kg + (size_t)row*D_ + c);
            cp16(Vd + row*HST + c, vg + (size_t)row*D_ + c);
        }
        asm volatile("cp.async.commit_group;\n");
    };

    #pragma unroll
    for (int it = 0; it < 2; ++it) {
        int id = it*256 + tid;
        int row = id >> 3, c = (id & 7) * 8;
        cp16(Qs + row*HST + c, qg + (size_t)row*D_ + c);
    }
    issueKV(0, 0);
    if (tid < 64) { mrow[tid] = -INFINITY; lrow[tid] = 0.0f; }

    float o[4][4] = {};
    const float scale = 0.125f;
    int nkt = qt + 1;

    for (int kt = 0; kt < nkt; ++kt) {
        int s = kt & 1;
        if (kt + 1 < nkt) {
            issueKV(kt+1, s^1);
            asm volatile("cp.async.wait_group 1;\n");
        } else {
            asm volatile("cp.async.wait_group 0;\n");
        }
        __syncthreads();
        u32 Ksm = base + KO + s*64*HST*2;
        u32 Vsm = base + VO + s*64*HST*2;
        int kBase = kt * 64;

        // Phase A: S = Q K^T   (k = d, 4 ksteps of 16)
        {
            float sacc[4][4] = {};
            #pragma unroll
            for (int ks = 0; ks < 4; ++ks) {
                int kb = ks*32;   // byte offset for 16 halfs
                u32 a0,a1,a2,a3;
                ldsm4(a0,a1,a2,a3, base + QO + (mr + arow)*144 + kb + ac);
                u32 bf[2][4];
                #pragma unroll
                for (int nt2 = 0; nt2 < 2; ++nt2)
                    ldsm4(bf[nt2][0], bf[nt2][1], bf[nt2][2], bf[nt2][3],
                          Ksm + (nbase + nt2*16 + brow)*144 + kb + bc);
                #pragma unroll
                for (int nt = 0; nt < 4; ++nt)
                    mma_f16(sacc[nt], a0,a1,a2,a3,
                            bf[nt>>1][(nt&1)*2], bf[nt>>1][(nt&1)*2+1]);
            }
            #pragma unroll
            for (int nt = 0; nt < 4; ++nt) {
                int nc = nbase + nt*8;
                #pragma unroll
                for (int f = 0; f < 4; ++f) {
                    int row = mr + lr + (f >> 1)*8;
                    int col = nc + lc*2 + (f & 1);
                    int qi = qBase + row, kj = kBase + col;
                    Ss[row*SST + col] = (kj <= qi) ? sacc[nt][f]*scale : -INFINITY;
                }
            }
        }
        __syncthreads();

        // Phase B: online softmax (fp32), P written as half
        {
            int row = tid >> 2, g = tid & 3;
            float sv[16];
            float lm = -INFINITY;
            #pragma unroll
            for (int j = 0; j < 16; ++j) {
                sv[j] = Ss[row*SST + g*16 + j];
                lm = fmaxf(lm, sv[j]);
            }
            lm = fmaxf(lm, __shfl_xor_sync(0xffffffffu, lm, 1));
            lm = fmaxf(lm, __shfl_xor_sync(0xffffffffu, lm, 2));
            float newm = fmaxf(mrow[row], lm);
            float ls = 0.0f;
            #pragma unroll
            for (int j = 0; j < 16; j += 2) {
                float p0 = __expf(sv[j]   - newm);
                float p1 = __expf(sv[j+1] - newm);
                ls += p0 + p1;
                *(__half2*)(Ps + row*HST + g*16 + j) = __floats2half2_rn(p0, p1);
            }
            ls += __shfl_xor_sync(0xffffffffu, ls, 1);
            ls += __shfl_xor_sync(0xffffffffu, ls, 2);
            if (g == 0) {
                float r = __expf(mrow[row] - newm);
                rrow[row] = r;
                lrow[row] = lrow[row] * r + ls;
                mrow[row] = newm;
            }
        }
        __syncthreads();

        // Phase C: O = O*r + P V   (k = key, 4 ksteps of 16; V via trans)
        {
            float r0 = rrow[mr + lr], r1 = rrow[mr + lr + 8];
            #pragma unroll
            for (int nt = 0; nt < 4; ++nt) {
                o[nt][0] *= r0; o[nt][1] *= r0;
                o[nt][2] *= r1; o[nt][3] *= r1;
            }
            #pragma unroll
            for (int ks = 0; ks < 4; ++ks) {
                int kk = ks*16;
                u32 a0,a1,a2,a3;
                ldsm4(a0,a1,a2,a3, base + PO + (mr + arow)*144 + kk*2 + ac);
                u32 bf[2][4];
                #pragma unroll
                for (int nt2 = 0; nt2 < 2; ++nt2)
                    ldsm4t(bf[nt2][0], bf[nt2][1], bf[nt2][2], bf[nt2][3],
                           Vsm + (kk + arow)*144 + (nbase + nt2*16)*2 + ac);
                #pragma unroll
                for (int nt = 0; nt < 4; ++nt)
                    mma_f16(o[nt], a0,a1,a2,a3,
                            bf[nt>>1][(nt&1)*2], bf[nt>>1][(nt&1)*2+1]);
            }
        }
        __syncthreads();
    }

    // Epilogue: normalize, write half to [b][t][h][d]
    #pragma unroll
    for (int half_ = 0; half_ < 2; ++half_) {
        int row = mr + lr + half_*8;
        float inv = 1.0f / lrow[row];
        int t = qBase + row;
        __half* og = g_atth + (((size_t)(b*T_ + t))*H_ + h)*D_;
        #pragma unroll
        for (int nt = 0; nt < 4; ++nt) {
            int d = nbase + nt*8 + lc*2;
            *(__half2*)(og + d) =
                __floats2half2_rn(o[nt][half_*2+0]*inv, o[nt][half_*2+1]*inv);
        }
    }
}

// ---------------------------------------------------------------------------
extern "C" void kernel_launch(void* const* d_in, const int* in_sizes, int n_in,
                              void* d_out, int out_size) {
    const float* x      = (const float*)d_in[0];
    const float* w_qkv  = (const float*)d_in[1];
    const float* w_proj = (const float*)d_in[2];
    const float* b_proj = (const float*)d_in[3];
    float* out = (float*)d_out;

    cudaFuncSetAttribute(attn_kernel,
                         cudaFuncAttributeMaxDynamicSharedMemorySize, ATTN_SMEM);
    cudaFuncSetAttribute(qkv_gemm,
                         cudaFuncAttributeMaxDynamicSharedMemorySize, GEMM_SMEM);
    cudaFuncSetAttribute(proj_gemm,
                         cudaFuncAttributeMaxDynamicSharedMemorySize, GEMM_SMEM);

    __half *xh_p, *wqh_p, *wph_p;
    cudaGetSymbolAddress((void**)&xh_p, g_xh);
    cudaGetSymbolAddress((void**)&wqh_p, g_wqh);
    cudaGetSymbolAddress((void**)&wph_p, g_wph);

    int n4x = M_*C_/4;
    to_half<<<(n4x+255)/256, 256>>>((const float4*)x, (__half2*)xh_p, n4x);
    transp_half<<<dim3(NQKV/32, C_/32), dim3(32,8)>>>(w_qkv, wqh_p, C_, NQKV);
    transp_half<<<dim3(C_/32, C_/32), dim3(32,8)>>>(w_proj, wph_p, C_, C_);

    qkv_gemm<<<dim3(NQKV/128, M_/128), 256, GEMM_SMEM>>>();
    attn_kernel<<<dim3(T_/64, B_*H_), 256, ATTN_SMEM>>>();
    proj_gemm<<<dim3(C_/128, M_/128), 256, GEMM_SMEM>>>(b_proj, out);
}

// round 11
// speedup vs baseline: 1.9332x; 1.2735x over previous
#include <cuda_runtime.h>
#include <cuda_fp16.h>
#include <math.h>

#define B_ 2
#define T_ 2048
#define C_ 1024
#define H_ 16
#define D_ 64
#define M_ (B_*T_)          // 4096
#define NQKV (3*C_)         // 3072

typedef unsigned int u32;

// Scratch (allocation-free rule: __device__ globals), all fp16
__device__ __align__(16) __half g_qh[(size_t)B_*H_*T_*D_];
__device__ __align__(16) __half g_kh[(size_t)B_*H_*T_*D_];
__device__ __align__(16) __half g_vh[(size_t)B_*H_*T_*D_];
__device__ __align__(16) __half g_atth[(size_t)M_*C_];   // [b][t][h][d]
__device__ __align__(16) __half g_xh[(size_t)M_*C_];     // x half         [M][K]
__device__ __align__(16) __half g_wqh[(size_t)NQKV*C_];  // w_qkv^T half   [N][K]
__device__ __align__(16) __half g_wph[(size_t)C_*C_];    // w_proj^T half  [N][K]

// ---------------------------------------------------------------------------
// Primitives
// ---------------------------------------------------------------------------
__device__ __forceinline__ void mma_f16(float c[4], u32 a0, u32 a1, u32 a2, u32 a3,
                                        u32 b0, u32 b1) {
    asm volatile("mma.sync.aligned.m16n8k16.row.col.f32.f16.f16.f32 "
                 "{%0,%1,%2,%3}, {%4,%5,%6,%7}, {%8,%9}, {%0,%1,%2,%3};"
                 : "+f"(c[0]), "+f"(c[1]), "+f"(c[2]), "+f"(c[3])
                 : "r"(a0), "r"(a1), "r"(a2), "r"(a3), "r"(b0), "r"(b1));
}
__device__ __forceinline__ void ldsm4(u32& r0, u32& r1, u32& r2, u32& r3, u32 addr) {
    asm volatile("ldmatrix.sync.aligned.m8n8.x4.shared.b16 {%0,%1,%2,%3}, [%4];"
                 : "=r"(r0), "=r"(r1), "=r"(r2), "=r"(r3) : "r"(addr));
}
__device__ __forceinline__ void ldsm4t(u32& r0, u32& r1, u32& r2, u32& r3, u32 addr) {
    asm volatile("ldmatrix.sync.aligned.m8n8.x4.trans.shared.b16 {%0,%1,%2,%3}, [%4];"
                 : "=r"(r0), "=r"(r1), "=r"(r2), "=r"(r3) : "r"(addr));
}
__device__ __forceinline__ void cp16(void* smem, const void* gmem) {
    u32 s = (u32)__cvta_generic_to_shared(smem);
    asm volatile("cp.async.cg.shared.global [%0], [%1], 16;\n" :: "r"(s), "l"(gmem));
}
__device__ __forceinline__ u32 packh2(float a, float b) {
    __half2 h = __floats2half2_rn(a, b);
    return *reinterpret_cast<u32*>(&h);
}

// ---------------------------------------------------------------------------
// Prep: one kernel. Blocks [0,4096): x->half. [4096,7168): w_qkv^T.
// [7168,8192): w_proj^T.
// ---------------------------------------------------------------------------
__global__ __launch_bounds__(256) void prep_all(const float* __restrict__ x,
                                                const float* __restrict__ wq,
                                                const float* __restrict__ wp) {
    __shared__ float t[32][33];
    int bid = blockIdx.x, tid = threadIdx.x;
    if (bid < 4096) {
        int i = bid*256 + tid;
        float4 v = ((const float4*)x)[i];
        __half2* d = (__half2*)g_xh;
        d[i*2+0] = __floats2half2_rn(v.x, v.y);
        d[i*2+1] = __floats2half2_rn(v.z, v.w);
        return;
    }
    const float* W; __half* Wt; int Kd, Nd, bx, by;
    if (bid < 7168) {
        int idx = bid - 4096;
        W = wq; Wt = g_wqh; Kd = C_; Nd = NQKV;
        bx = (idx % 96) * 32; by = (idx / 96) * 32;
    } else {
        int idx = bid - 7168;
        W = wp; Wt = g_wph; Kd = C_; Nd = C_;
        bx = (idx & 31) * 32; by = (idx >> 5) * 32;
    }
    int tx = tid & 31, ty = tid >> 5;
    #pragma unroll
    for (int i = 0; i < 32; i += 8)
        t[ty+i][tx] = W[(size_t)(by+ty+i)*Nd + bx+tx];
    __syncthreads();
    #pragma unroll
    for (int i = 0; i < 32; i += 8)
        Wt[(size_t)(bx+ty+i)*Kd + by+tx] = __float2half_rn(t[tx][ty+i]);
}

// ---------------------------------------------------------------------------
// fp16 tensor GEMM: 128x128 tile, BK=64, 256 threads (8 warps 2m x 4n),
// 2-stage cp.async, ldmatrix fragments. Row stride 72 halfs (144B).
// ---------------------------------------------------------------------------
#define ASTR 72
#define TILE_B (128*ASTR*2)            // 18432 per operand
#define STG_B (2*TILE_B)               // 36864 per stage
#define GEMM_SMEM (2*STG_B)            // 73728
#define NIT (C_/64)                    // 16

struct GemmFrags { float c[4][4][4]; };    // [mt][nt][frag]

__device__ __forceinline__ void gemm_f16_body(const __half* __restrict__ A,
                                              const __half* __restrict__ Bw,
                                              char* smem, int m0, int n0,
                                              GemmFrags& F) {
    int tid = threadIdx.x;
    int lane = tid & 31, wid = tid >> 5;
    int warp_m = wid >> 2, warp_n = wid & 3;    // 2 x 4
    u32 base = (u32)__cvta_generic_to_shared(smem);

    int l8 = lane & 7;
    int arow = l8 + ((lane >> 3) & 1) * 8, ac = (lane >> 4) * 16;
    int brow = l8 + (lane >> 4) * 8,       bc = ((lane >> 3) & 1) * 16;

    auto issue = [&](int k0, int s) {
        __half* Ab = (__half*)(smem + s*STG_B);
        __half* Bb = (__half*)(smem + s*STG_B + TILE_B);
        #pragma unroll
        for (int it = 0; it < 4; ++it) {
            int id = it*256 + tid;
            int row = id >> 3, c = (id & 7) * 8;
            cp16(Ab + row*ASTR + c, A + (size_t)(m0 + row)*C_ + k0 + c);
            cp16(Bb + row*ASTR + c, Bw + (size_t)(n0 + row)*C_ + k0 + c);
        }
        asm volatile("cp.async.commit_group;\n");
    };

    issue(0, 0);
    for (int it = 0; it < NIT; ++it) {
        asm volatile("cp.async.wait_group 0;\n");
        __syncthreads();
        if (it + 1 < NIT) issue((it+1)*64, (it+1) & 1);
        u32 Ab = base + (it & 1)*STG_B;
        u32 Bb = Ab + TILE_B;
        #pragma unroll
        for (int ks = 0; ks < 4; ++ks) {
            int kb = ks*32;   // 16 halfs per kstep
            u32 af[4][4], bf[2][4];
            #pragma unroll
            for (int mt = 0; mt < 4; ++mt)
                ldsm4(af[mt][0], af[mt][1], af[mt][2], af[mt][3],
                      Ab + (warp_m*64 + mt*16 + arow)*144 + kb + ac);
            #pragma unroll
            for (int nt2 = 0; nt2 < 2; ++nt2)
                ldsm4(bf[nt2][0], bf[nt2][1], bf[nt2][2], bf[nt2][3],
                      Bb + (warp_n*32 + nt2*16 + brow)*144 + kb + bc);
            #pragma unroll
            for (int mt = 0; mt < 4; ++mt)
                #pragma unroll
                for (int nt = 0; nt < 4; ++nt)
                    mma_f16(F.c[mt][nt], af[mt][0], af[mt][1], af[mt][2], af[mt][3],
                            bf[nt>>1][(nt&1)*2], bf[nt>>1][(nt&1)*2+1]);
        }
        __syncthreads();
    }
}

__global__ __launch_bounds__(256, 2) void qkv_gemm() {
    extern __shared__ char smg[];
    int tid = threadIdx.x;
    int lane = tid & 31, wid = tid >> 5;
    int warp_m = wid >> 2, warp_n = wid & 3;
    int lr = lane >> 2, lc = lane & 3;
    int m0 = blockIdx.y * 128, n0 = blockIdx.x * 128;

    GemmFrags F = {};
    gemm_f16_body(g_xh, g_wqh, smg, m0, n0, F);

    #pragma unroll
    for (int mt = 0; mt < 4; ++mt) {
        #pragma unroll
        for (int nt = 0; nt < 4; ++nt) {
            #pragma unroll
            for (int f = 0; f < 4; ++f) {
                int m = m0 + warp_m*64 + mt*16 + lr + (f >> 1)*8;
                int n = n0 + warp_n*32 + nt*8 + lc*2 + (f & 1);
                int bb = m >> 11, t = m & 2047;
                int three = n % 3;
                int hd = n / 3;
                int h = hd >> 6, d = hd & 63;
                size_t dst = (((size_t)(bb*H_ + h))*T_ + t)*D_ + d;
                __half v = __float2half_rn(F.c[mt][nt][f]);
                if (three == 0)      g_qh[dst] = v;
                else if (three == 1) g_kh[dst] = v;
                else                 g_vh[dst] = v;
            }
        }
    }
}

__global__ __launch_bounds__(256, 2) void proj_gemm(const float* __restrict__ bias,
                                                    float* __restrict__ out) {
    extern __shared__ char smg[];
    int tid = threadIdx.x;
    int lane = tid & 31, wid = tid >> 5;
    int warp_m = wid >> 2, warp_n = wid & 3;
    int lr = lane >> 2, lc = lane & 3;
    int m0 = blockIdx.y * 128, n0 = blockIdx.x * 128;

    GemmFrags F = {};
    gemm_f16_body(g_atth, g_wph, smg, m0, n0, F);

    #pragma unroll
    for (int mt = 0; mt < 4; ++mt) {
        #pragma unroll
        for (int nt = 0; nt < 4; ++nt) {
            #pragma unroll
            for (int f = 0; f < 4; ++f) {
                int m = m0 + warp_m*64 + mt*16 + lr + (f >> 1)*8;
                int n = n0 + warp_n*32 + nt*8 + lc*2 + (f & 1);
                out[(size_t)m * C_ + n] = F.c[mt][nt][f] + bias[n];
            }
        }
    }
}

// ---------------------------------------------------------------------------
// Flash attention, FA-2 register style: BQ=128, BK=64, 256 threads = 8 warps,
// warp tile 16(q) x 64(keys/d). S/P in registers; softmax via quad shuffles.
// ONE barrier per KV tile; prefetch issued AFTER the barrier (race-free: all
// warps have finished reading the target buffer once the barrier passes).
// ---------------------------------------------------------------------------
#define AHST 72
#define AQO 0
#define AKO (AQO + 128*AHST*2)          // 18432
#define AVO (AKO + 2*64*AHST*2)         // 36864
#define ATTN_SMEM (AVO + 2*64*AHST*2)   // 55296

__global__ __launch_bounds__(256, 2) void attn_kernel() {
    extern __shared__ char smc[];
    __half* Qs = (__half*)(smc + AQO);
    __half* Kb = (__half*)(smc + AKO);
    __half* Vb = (__half*)(smc + AVO);
    u32 base = (u32)__cvta_generic_to_shared(smc);

    int tid = threadIdx.x;
    int lane = tid & 31, wid = tid >> 5;      // warp owns q rows [16*wid, 16*wid+16)
    int lr = lane >> 2, lc = lane & 3;
    int l8 = lane & 7;
    int arow = l8 + ((lane >> 3) & 1) * 8, ac = (lane >> 4) * 16;
    int brow = l8 + (lane >> 4) * 8,       bc = ((lane >> 3) & 1) * 16;

    int bh = blockIdx.y;
    int b = bh >> 4, h = bh & 15;
    int qt = gridDim.x - 1 - blockIdx.x;       // heavy CTAs first
    int qBase = qt * 128;
    int rbase = qBase + wid*16;                // this warp's first q row

    const __half* qg  = g_qh + (((size_t)(b*H_ + h))*T_ + qBase)*D_;
    const __half* kgb = g_kh + ((size_t)(b*H_ + h))*T_*D_;
    const __half* vgb = g_vh + ((size_t)(b*H_ + h))*T_*D_;

    auto issueKV = [&](int kt, int s) {
        const __half* kg = kgb + (size_t)kt*64*D_;
        const __half* vg = vgb + (size_t)kt*64*D_;
        __half* Kd = Kb + s*64*AHST;
        __half* Vd = Vb + s*64*AHST;
        #pragma unroll
        for (int it = 0; it < 2; ++it) {
            int id = it*256 + tid;
            int row = id >> 3, c = (id & 7) * 8;
            cp16(Kd + row*AHST + c, kg + (size_t)row*D_ + c);
            cp16(Vd + row*AHST + c, vg + (size_t)row*D_ + c);
        }
        asm volatile("cp.async.commit_group;\n");
    };

    // group 0: Q (128 rows) + KV tile 0
    #pragma unroll
    for (int it = 0; it < 4; ++it) {
        int id = it*256 + tid;
        int row = id >> 3, c = (id & 7) * 8;
        cp16(Qs + row*AHST + c, qg + (size_t)row*D_ + c);
    }
    issueKV(0, 0);

    u32 qf[4][4];                       // Q fragments, loaded once
    float o[8][4] = {};
    float m0v = -INFINITY, m1v = -INFINITY, l0v = 0.0f, l1v = 0.0f;
    const float scale = 0.125f;
    int nkt = 2*qt + 2;

    for (int kt = 0; kt < nkt; ++kt) {
        int s = kt & 1;
        asm volatile("cp.async.wait_group 0;\n");   // tile kt (+Q on kt=0) ready
        __syncthreads();                            // all warps done with buffer s^1
        if (kt + 1 < nkt) issueKV(kt+1, s^1);       // safe: nobody reads s^1 anymore
        if (kt == 0) {
            #pragma unroll
            for (int ks = 0; ks < 4; ++ks)
                ldsm4(qf[ks][0], qf[ks][1], qf[ks][2], qf[ks][3],
                      base + AQO + (wid*16 + arow)*144 + ks*32 + ac);
        }
        u32 Ksm = base + AKO + s*64*AHST*2;
        u32 Vsm = base + AVO + s*64*AHST*2;
        int kBase = kt * 64;

        // Phase A: S = Q K^T  (all 64 keys in this warp)
        float s8[8][4] = {};
        #pragma unroll
        for (int ks = 0; ks < 4; ++ks) {
            int kb = ks*32;
            u32 bf[4][4];
            #pragma unroll
            for (int j = 0; j < 4; ++j)
                ldsm4(bf[j][0], bf[j][1], bf[j][2], bf[j][3],
                      Ksm + (j*16 + brow)*144 + kb + bc);
            #pragma unroll
            for (int nt = 0; nt < 8; ++nt)
                mma_f16(s8[nt], qf[ks][0], qf[ks][1], qf[ks][2], qf[ks][3],
                        bf[nt>>1][(nt&1)*2], bf[nt>>1][(nt&1)*2+1]);
        }

        // Scale + causal mask (register)
        bool need_mask = (kBase + 63 > rbase);
        if (need_mask) {
            #pragma unroll
            for (int nt = 0; nt < 8; ++nt)
                #pragma unroll
                for (int f = 0; f < 4; ++f) {
                    int row = rbase + lr + (f >> 1)*8;
                    int col = kBase + nt*8 + lc*2 + (f & 1);
                    s8[nt][f] = (col <= row) ? s8[nt][f]*scale : -INFINITY;
                }
        } else {
            #pragma unroll
            for (int nt = 0; nt < 8; ++nt)
                #pragma unroll
                for (int f = 0; f < 4; ++f) s8[nt][f] *= scale;
        }

        // Register softmax (quad shuffles; rows lr and lr+8)
        float lm0 = -INFINITY, lm1 = -INFINITY;
        #pragma unroll
        for (int nt = 0; nt < 8; ++nt) {
            lm0 = fmaxf(lm0, fmaxf(s8[nt][0], s8[nt][1]));
            lm1 = fmaxf(lm1, fmaxf(s8[nt][2], s8[nt][3]));
        }
        lm0 = fmaxf(lm0, __shfl_xor_sync(0xffffffffu, lm0, 1));
        lm0 = fmaxf(lm0, __shfl_xor_sync(0xffffffffu, lm0, 2));
        lm1 = fmaxf(lm1, __shfl_xor_sync(0xffffffffu, lm1, 1));
        lm1 = fmaxf(lm1, __shfl_xor_sync(0xffffffffu, lm1, 2));
        float nm0 = fmaxf(m0v, lm0), nm1 = fmaxf(m1v, lm1);
        float r0 = __expf(m0v - nm0), r1 = __expf(m1v - nm1);
        float ls0 = 0.0f, ls1 = 0.0f;
        #pragma unroll
        for (int nt = 0; nt < 8; ++nt) {
            s8[nt][0] = __expf(s8[nt][0] - nm0); ls0 += s8[nt][0];
            s8[nt][1] = __expf(s8[nt][1] - nm0); ls0 += s8[nt][1];
            s8[nt][2] = __expf(s8[nt][2] - nm1); ls1 += s8[nt][2];
            s8[nt][3] = __expf(s8[nt][3] - nm1); ls1 += s8[nt][3];
        }
        ls0 += __shfl_xor_sync(0xffffffffu, ls0, 1);
        ls0 += __shfl_xor_sync(0xffffffffu, ls0, 2);
        ls1 += __shfl_xor_sync(0xffffffffu, ls1, 1);
        ls1 += __shfl_xor_sync(0xffffffffu, ls1, 2);
        l0v = l0v*r0 + ls0; m0v = nm0;
        l1v = l1v*r1 + ls1; m1v = nm1;
        #pragma unroll
        for (int nt = 0; nt < 8; ++nt) {
            o[nt][0] *= r0; o[nt][1] *= r0;
            o[nt][2] *= r1; o[nt][3] *= r1;
        }

        // P fragments directly from S fragments (A-operand layout match)
        u32 pf[4][4];
        #pragma unroll
        for (int ks = 0; ks < 4; ++ks) {
            pf[ks][0] = packh2(s8[2*ks  ][0], s8[2*ks  ][1]);
            pf[ks][1] = packh2(s8[2*ks  ][2], s8[2*ks  ][3]);
            pf[ks][2] = packh2(s8[2*ks+1][0], s8[2*ks+1][1]);
            pf[ks][3] = packh2(s8[2*ks+1][2], s8[2*ks+1][3]);
        }

        // Phase C: O += P V  (V transposed via ldsm4t)
        #pragma unroll
        for (int ks = 0; ks < 4; ++ks) {
            int kk = ks*16;
            u32 vf[4][4];
            #pragma unroll
            for (int j = 0; j < 4; ++j)
                ldsm4t(vf[j][0], vf[j][1], vf[j][2], vf[j][3],
                       Vsm + (kk + arow)*144 + (j*16)*2 + ac);
            #pragma unroll
            for (int nt = 0; nt < 8; ++nt)
                mma_f16(o[nt], pf[ks][0], pf[ks][1], pf[ks][2], pf[ks][3],
                        vf[nt>>1][(nt&1)*2], vf[nt>>1][(nt&1)*2+1]);
        }
    }

    // Epilogue: normalize, write half to [b][t][h][d]
    float inv0 = 1.0f / l0v, inv1 = 1.0f / l1v;
    int t0 = rbase + lr, t1 = t0 + 8;
    __half* og0 = g_atth + (((size_t)(b*T_ + t0))*H_ + h)*D_;
    __half* og1 = g_atth + (((size_t)(b*T_ + t1))*H_ + h)*D_;
    #pragma unroll
    for (int nt = 0; nt < 8; ++nt) {
        int d = nt*8 + lc*2;
        *(__half2*)(og0 + d) = __floats2half2_rn(o[nt][0]*inv0, o[nt][1]*inv0);
        *(__half2*)(og1 + d) = __floats2half2_rn(o[nt][2]*inv1, o[nt][3]*inv1);
    }
}

// ---------------------------------------------------------------------------
extern "C" void kernel_launch(void* const* d_in, const int* in_sizes, int n_in,
                              void* d_out, int out_size) {
    const float* x      = (const float*)d_in[0];
    const float* w_qkv  = (const float*)d_in[1];
    const float* w_proj = (const float*)d_in[2];
    const float* b_proj = (const float*)d_in[3];
    float* out = (float*)d_out;

    cudaFuncSetAttribute(attn_kernel,
                         cudaFuncAttributeMaxDynamicSharedMemorySize, ATTN_SMEM);
    cudaFuncSetAttribute(qkv_gemm,
                         cudaFuncAttributeMaxDynamicSharedMemorySize, GEMM_SMEM);
    cudaFuncSetAttribute(proj_gemm,
                         cudaFuncAttributeMaxDynamicSharedMemorySize, GEMM_SMEM);

    prep_all<<<8192, 256>>>(x, w_qkv, w_proj);
    qkv_gemm<<<dim3(NQKV/128, M_/128), 256, GEMM_SMEM>>>();
    attn_kernel<<<dim3(T_/128, B_*H_), 256, ATTN_SMEM>>>();
    proj_gemm<<<dim3(C_/128, M_/128), 256, GEMM_SMEM>>>(b_proj, out);
}

// round 12
// speedup vs baseline: 1.9614x; 1.0146x over previous
#include <cuda_runtime.h>
#include <cuda_fp16.h>
#include <math.h>

#define B_ 2
#define T_ 2048
#define C_ 1024
#define H_ 16
#define D_ 64
#define M_ (B_*T_)          // 4096
#define NQKV (3*C_)         // 3072

typedef unsigned int u32;

// Scratch (allocation-free rule: __device__ globals), all fp16
__device__ __align__(16) __half g_qh[(size_t)B_*H_*T_*D_];
__device__ __align__(16) __half g_kh[(size_t)B_*H_*T_*D_];
__device__ __align__(16) __half g_vh[(size_t)B_*H_*T_*D_];
__device__ __align__(16) __half g_atth[(size_t)M_*C_];   // [b][t][h][d]
__device__ __align__(16) __half g_xh[(size_t)M_*C_];     // x half        [M][K]
__device__ __align__(16) __half g_wqh[(size_t)C_*NQKV];  // w_qkv half    [K][N]
__device__ __align__(16) __half g_wph[(size_t)C_*C_];    // w_proj half   [K][N]

// ---------------------------------------------------------------------------
// Primitives
// ---------------------------------------------------------------------------
__device__ __forceinline__ void mma_f16(float c[4], u32 a0, u32 a1, u32 a2, u32 a3,
                                        u32 b0, u32 b1) {
    asm volatile("mma.sync.aligned.m16n8k16.row.col.f32.f16.f16.f32 "
                 "{%0,%1,%2,%3}, {%4,%5,%6,%7}, {%8,%9}, {%0,%1,%2,%3};"
                 : "+f"(c[0]), "+f"(c[1]), "+f"(c[2]), "+f"(c[3])
                 : "r"(a0), "r"(a1), "r"(a2), "r"(a3), "r"(b0), "r"(b1));
}
__device__ __forceinline__ void ldsm4(u32& r0, u32& r1, u32& r2, u32& r3, u32 addr) {
    asm volatile("ldmatrix.sync.aligned.m8n8.x4.shared.b16 {%0,%1,%2,%3}, [%4];"
                 : "=r"(r0), "=r"(r1), "=r"(r2), "=r"(r3) : "r"(addr));
}
__device__ __forceinline__ void ldsm4t(u32& r0, u32& r1, u32& r2, u32& r3, u32 addr) {
    asm volatile("ldmatrix.sync.aligned.m8n8.x4.trans.shared.b16 {%0,%1,%2,%3}, [%4];"
                 : "=r"(r0), "=r"(r1), "=r"(r2), "=r"(r3) : "r"(addr));
}
__device__ __forceinline__ void cp16(void* smem, const void* gmem) {
    u32 s = (u32)__cvta_generic_to_shared(smem);
    asm volatile("cp.async.cg.shared.global [%0], [%1], 16;\n" :: "r"(s), "l"(gmem));
}
__device__ __forceinline__ u32 packh2(float a, float b) {
    __half2 h = __floats2half2_rn(a, b);
    return *reinterpret_cast<u32*>(&h);
}
__device__ __forceinline__ float ex2f(float x) {
    float r; asm("ex2.approx.f32 %0, %1;" : "=f"(r) : "f"(x)); return r;
}

// ---------------------------------------------------------------------------
// Prep: pure streaming fp32->fp16 converts (no transpose).
// Blocks [0,4096): x. [4096,7168): w_qkv. [7168,8192): w_proj.
// ---------------------------------------------------------------------------
__global__ __launch_bounds__(256) void prep_all(const float* __restrict__ x,
                                                const float* __restrict__ wq,
                                                const float* __restrict__ wp) {
    int bid = blockIdx.x, tid = threadIdx.x;
    const float4* src; __half2* dst; int i;
    if (bid < 4096)      { src = (const float4*)x;  dst = (__half2*)g_xh;  i = bid*256 + tid; }
    else if (bid < 7168) { src = (const float4*)wq; dst = (__half2*)g_wqh; i = (bid-4096)*256 + tid; }
    else                 { src = (const float4*)wp; dst = (__half2*)g_wph; i = (bid-7168)*256 + tid; }
    float4 v = src[i];
    dst[i*2+0] = __floats2half2_rn(v.x, v.y);
    dst[i*2+1] = __floats2half2_rn(v.z, v.w);
}

// ---------------------------------------------------------------------------
// fp16 tensor GEMM: 128x128 tile, BK=64, 256 threads (8 warps 2m x 4n),
// 2-stage cp.async, ONE barrier per k-tile. A [M][K] via ldsm4, B [K][N]
// via ldsm4t (V-path pattern). A stride 144B, B stride 272B: conflict-free.
// ---------------------------------------------------------------------------
#define ASTR 72                        // halfs, A row stride
#define BSTR 136                       // halfs, B row stride
#define TILE_A (128*ASTR*2)            // 18432
#define TILE_BB (64*BSTR*2)            // 17408
#define STG_B (TILE_A + TILE_BB)       // 35840
#define GEMM_SMEM (2*STG_B)            // 71680
#define NIT (C_/64)                    // 16

struct GemmFrags { float c[4][4][4]; };    // [mt][nt][frag]

template<int NDIM>
__device__ __forceinline__ void gemm_f16_body(const __half* __restrict__ A,
                                              const __half* __restrict__ Bw,
                                              char* smem, int m0, int n0,
                                              GemmFrags& F) {
    int tid = threadIdx.x;
    int lane = tid & 31, wid = tid >> 5;
    int warp_m = wid >> 2, warp_n = wid & 3;    // 2 x 4
    u32 base = (u32)__cvta_generic_to_shared(smem);

    int l8 = lane & 7;
    int arow = l8 + ((lane >> 3) & 1) * 8, ac = (lane >> 4) * 16;

    auto issue = [&](int k0, int s) {
        __half* Ab = (__half*)(smem + s*STG_B);
        __half* Bb = (__half*)(smem + s*STG_B + TILE_A);
        #pragma unroll
        for (int it = 0; it < 4; ++it) {
            int id = it*256 + tid;
            int row = id >> 3, c = (id & 7) * 8;
            cp16(Ab + row*ASTR + c, A + (size_t)(m0 + row)*C_ + k0 + c);
        }
        #pragma unroll
        for (int it = 0; it < 4; ++it) {
            int id = it*256 + tid;
            int krow = id >> 4, c = (id & 15) * 8;
            cp16(Bb + krow*BSTR + c, Bw + (size_t)(k0 + krow)*NDIM + n0 + c);
        }
        asm volatile("cp.async.commit_group;\n");
    };

    issue(0, 0);
    for (int it = 0; it < NIT; ++it) {
        int s = it & 1;
        asm volatile("cp.async.wait_group 0;\n");
        __syncthreads();                          // all warps done with buffer s^1
        if (it + 1 < NIT) issue((it+1)*64, s^1);  // safe: nobody reads s^1 anymore
        u32 Ab = base + s*STG_B;
        u32 Bb = Ab + TILE_A;
        #pragma unroll
        for (int ks = 0; ks < 4; ++ks) {
            int kk = ks*16;
            u32 af[4][4], bf[2][4];
            #pragma unroll
            for (int mt = 0; mt < 4; ++mt)
                ldsm4(af[mt][0], af[mt][1], af[mt][2], af[mt][3],
                      Ab + (warp_m*64 + mt*16 + arow)*144 + kk*2 + ac);
            #pragma unroll
            for (int j = 0; j < 2; ++j)
                ldsm4t(bf[j][0], bf[j][1], bf[j][2], bf[j][3],
                       Bb + (kk + arow)*272 + (warp_n*32 + j*16)*2 + ac);
            #pragma unroll
            for (int mt = 0; mt < 4; ++mt)
                #pragma unroll
                for (int nt = 0; nt < 4; ++nt)
                    mma_f16(F.c[mt][nt], af[mt][0], af[mt][1], af[mt][2], af[mt][3],
                            bf[nt>>1][(nt&1)*2], bf[nt>>1][(nt&1)*2+1]);
        }
    }
}

__global__ __launch_bounds__(256, 2) void qkv_gemm() {
    extern __shared__ char smg[];
    int tid = threadIdx.x;
    int lane = tid & 31, wid = tid >> 5;
    int warp_m = wid >> 2, warp_n = wid & 3;
    int lr = lane >> 2, lc = lane & 3;
    int m0 = blockIdx.y * 128, n0 = blockIdx.x * 128;

    GemmFrags F = {};
    gemm_f16_body<NQKV>(g_xh, g_wqh, smg, m0, n0, F);

    #pragma unroll
    for (int mt = 0; mt < 4; ++mt) {
        #pragma unroll
        for (int nt = 0; nt < 4; ++nt) {
            #pragma unroll
            for (int f = 0; f < 4; ++f) {
                int m = m0 + warp_m*64 + mt*16 + lr + (f >> 1)*8;
                int n = n0 + warp_n*32 + nt*8 + lc*2 + (f & 1);
                int bb = m >> 11, t = m & 2047;
                int three = n % 3;
                int hd = n / 3;
                int h = hd >> 6, d = hd & 63;
                size_t dst = (((size_t)(bb*H_ + h))*T_ + t)*D_ + d;
                __half v = __float2half_rn(F.c[mt][nt][f]);
                if (three == 0)      g_qh[dst] = v;
                else if (three == 1) g_kh[dst] = v;
                else                 g_vh[dst] = v;
            }
        }
    }
}

__global__ __launch_bounds__(256, 2) void proj_gemm(const float* __restrict__ bias,
                                                    float* __restrict__ out) {
    extern __shared__ char smg[];
    int tid = threadIdx.x;
    int lane = tid & 31, wid = tid >> 5;
    int warp_m = wid >> 2, warp_n = wid & 3;
    int lr = lane >> 2, lc = lane & 3;
    int m0 = blockIdx.y * 128, n0 = blockIdx.x * 128;

    GemmFrags F = {};
    gemm_f16_body<C_>(g_atth, g_wph, smg, m0, n0, F);

    #pragma unroll
    for (int mt = 0; mt < 4; ++mt) {
        #pragma unroll
        for (int nt = 0; nt < 4; ++nt) {
            #pragma unroll
            for (int f = 0; f < 4; ++f) {
                int m = m0 + warp_m*64 + mt*16 + lr + (f >> 1)*8;
                int n = n0 + warp_n*32 + nt*8 + lc*2 + (f & 1);
                out[(size_t)m * C_ + n] = F.c[mt][nt][f] + bias[n];
            }
        }
    }
}

// ---------------------------------------------------------------------------
// Flash attention, FA-2 register style (round-11, race-free ordering),
// softmax in base-2 (scale*log2e folded; raw ex2.approx).
// ---------------------------------------------------------------------------
#define AHST 72
#define AQO 0
#define AKO (AQO + 128*AHST*2)          // 18432
#define AVO (AKO + 2*64*AHST*2)         // 36864
#define ATTN_SMEM (AVO + 2*64*AHST*2)   // 55296

__global__ __launch_bounds__(256, 2) void attn_kernel() {
    extern __shared__ char smc[];
    __half* Qs = (__half*)(smc + AQO);
    __half* Kb = (__half*)(smc + AKO);
    __half* Vb = (__half*)(smc + AVO);
    u32 base = (u32)__cvta_generic_to_shared(smc);

    int tid = threadIdx.x;
    int lane = tid & 31, wid = tid >> 5;
    int lr = lane >> 2, lc = lane & 3;
    int l8 = lane & 7;
    int arow = l8 + ((lane >> 3) & 1) * 8, ac = (lane >> 4) * 16;
    int brow = l8 + (lane >> 4) * 8,       bc = ((lane >> 3) & 1) * 16;

    int bh = blockIdx.y;
    int b = bh >> 4, h = bh & 15;
    int qt = gridDim.x - 1 - blockIdx.x;       // heavy CTAs first
    int qBase = qt * 128;
    int rbase = qBase + wid*16;

    const __half* qg  = g_qh + (((size_t)(b*H_ + h))*T_ + qBase)*D_;
    const __half* kgb = g_kh + ((size_t)(b*H_ + h))*T_*D_;
    const __half* vgb = g_vh + ((size_t)(b*H_ + h))*T_*D_;

    auto issueKV = [&](int kt, int s) {
        const __half* kg = kgb + (size_t)kt*64*D_;
        const __half* vg = vgb + (size_t)kt*64*D_;
        __half* Kd = Kb + s*64*AHST;
        __half* Vd = Vb + s*64*AHST;
        #pragma unroll
        for (int it = 0; it < 2; ++it) {
            int id = it*256 + tid;
            int row = id >> 3, c = (id & 7) * 8;
            cp16(Kd + row*AHST + c, kg + (size_t)row*D_ + c);
            cp16(Vd + row*AHST + c, vg + (size_t)row*D_ + c);
        }
        asm volatile("cp.async.commit_group;\n");
    };

    #pragma unroll
    for (int it = 0; it < 4; ++it) {
        int id = it*256 + tid;
        int row = id >> 3, c = (id & 7) * 8;
        cp16(Qs + row*AHST + c, qg + (size_t)row*D_ + c);
    }
    issueKV(0, 0);

    u32 qf[4][4];
    float o[8][4] = {};
    float m0v = -INFINITY, m1v = -INFINITY, l0v = 0.0f, l1v = 0.0f;
    const float scale2 = 0.125f * 1.4426950408889634f;   // scale * log2(e)
    int nkt = 2*qt + 2;

    for (int kt = 0; kt < nkt; ++kt) {
        int s = kt & 1;
        asm volatile("cp.async.wait_group 0;\n");
        __syncthreads();
        if (kt + 1 < nkt) issueKV(kt+1, s^1);
        if (kt == 0) {
            #pragma unroll
            for (int ks = 0; ks < 4; ++ks)
                ldsm4(qf[ks][0], qf[ks][1], qf[ks][2], qf[ks][3],
                      base + AQO + (wid*16 + arow)*144 + ks*32 + ac);
        }
        u32 Ksm = base + AKO + s*64*AHST*2;
        u32 Vsm = base + AVO + s*64*AHST*2;
        int kBase = kt * 64;

        // Phase A: S = Q K^T
        float s8[8][4] = {};
        #pragma unroll
        for (int ks = 0; ks < 4; ++ks) {
            int kb = ks*32;
            u32 bf[4][4];
            #pragma unroll
            for (int j = 0; j < 4; ++j)
                ldsm4(bf[j][0], bf[j][1], bf[j][2], bf[j][3],
                      Ksm + (j*16 + brow)*144 + kb + bc);
            #pragma unroll
            for (int nt = 0; nt < 8; ++nt)
                mma_f16(s8[nt], qf[ks][0], qf[ks][1], qf[ks][2], qf[ks][3],
                        bf[nt>>1][(nt&1)*2], bf[nt>>1][(nt&1)*2+1]);
        }

        // Scale (base-2 domain) + causal mask
        bool need_mask = (kBase + 63 > rbase);
        if (need_mask) {
            #pragma unroll
            for (int nt = 0; nt < 8; ++nt)
                #pragma unroll
                for (int f = 0; f < 4; ++f) {
                    int row = rbase + lr + (f >> 1)*8;
                    int col = kBase + nt*8 + lc*2 + (f & 1);
                    s8[nt][f] = (col <= row) ? s8[nt][f]*scale2 : -INFINITY;
                }
        } else {
            #pragma unroll
            for (int nt = 0; nt < 8; ++nt)
                #pragma unroll
                for (int f = 0; f < 4; ++f) s8[nt][f] *= scale2;
        }

        // Register softmax in base-2 (quad shuffles; rows lr and lr+8)
        float lm0 = -INFINITY, lm1 = -INFINITY;
        #pragma unroll
        for (int nt = 0; nt < 8; ++nt) {
            lm0 = fmaxf(lm0, fmaxf(s8[nt][0], s8[nt][1]));
            lm1 = fmaxf(lm1, fmaxf(s8[nt][2], s8[nt][3]));
        }
        lm0 = fmaxf(lm0, __shfl_xor_sync(0xffffffffu, lm0, 1));
        lm0 = fmaxf(lm0, __shfl_xor_sync(0xffffffffu, lm0, 2));
        lm1 = fmaxf(lm1, __shfl_xor_sync(0xffffffffu, lm1, 1));
        lm1 = fmaxf(lm1, __shfl_xor_sync(0xffffffffu, lm1, 2));
        float nm0 = fmaxf(m0v, lm0), nm1 = fmaxf(m1v, lm1);
        float r0 = ex2f(m0v - nm0), r1 = ex2f(m1v - nm1);
        float ls0 = 0.0f, ls1 = 0.0f;
        #pragma unroll
        for (int nt = 0; nt < 8; ++nt) {
            s8[nt][0] = ex2f(s8[nt][0] - nm0); ls0 += s8[nt][0];
            s8[nt][1] = ex2f(s8[nt][1] - nm0); ls0 += s8[nt][1];
            s8[nt][2] = ex2f(s8[nt][2] - nm1); ls1 += s8[nt][2];
            s8[nt][3] = ex2f(s8[nt][3] - nm1); ls1 += s8[nt][3];
        }
        ls0 += __shfl_xor_sync(0xffffffffu, ls0, 1);
        ls0 += __shfl_xor_sync(0xffffffffu, ls0, 2);
        ls1 += __shfl_xor_sync(0xffffffffu, ls1, 1);
        ls1 += __shfl_xor_sync(0xffffffffu, ls1, 2);
        l0v = l0v*r0 + ls0; m0v = nm0;
        l1v = l1v*r1 + ls1; m1v = nm1;
        #pragma unroll
        for (int nt = 0; nt < 8; ++nt) {
            o[nt][0] *= r0; o[nt][1] *= r0;
            o[nt][2] *= r1; o[nt][3] *= r1;
        }

        // P fragments directly from S fragments
        u32 pf[4][4];
        #pragma unroll
        for (int ks = 0; ks < 4; ++ks) {
            pf[ks][0] = packh2(s8[2*ks  ][0], s8[2*ks  ][1]);
            pf[ks][1] = packh2(s8[2*ks  ][2], s8[2*ks  ][3]);
            pf[ks][2] = packh2(s8[2*ks+1][0], s8[2*ks+1][1]);
            pf[ks][3] = packh2(s8[2*ks+1][2], s8[2*ks+1][3]);
        }

        // Phase C: O += P V
        #pragma unroll
        for (int ks = 0; ks < 4; ++ks) {
            int kk = ks*16;
            u32 vf[4][4];
            #pragma unroll
            for (int j = 0; j < 4; ++j)
                ldsm4t(vf[j][0], vf[j][1], vf[j][2], vf[j][3],
                       Vsm + (kk + arow)*144 + (j*16)*2 + ac);
            #pragma unroll
            for (int nt = 0; nt < 8; ++nt)
                mma_f16(o[nt], pf[ks][0], pf[ks][1], pf[ks][2], pf[ks][3],
                        vf[nt>>1][(nt&1)*2], vf[nt>>1][(nt&1)*2+1]);
        }
    }

    // Epilogue
    float inv0 = 1.0f / l0v, inv1 = 1.0f / l1v;
    int t0 = rbase + lr, t1 = t0 + 8;
    __half* og0 = g_atth + (((size_t)(b*T_ + t0))*H_ + h)*D_;
    __half* og1 = g_atth + (((size_t)(b*T_ + t1))*H_ + h)*D_;
    #pragma unroll
    for (int nt = 0; nt < 8; ++nt) {
        int d = nt*8 + lc*2;
        *(__half2*)(og0 + d) = __floats2half2_rn(o[nt][0]*inv0, o[nt][1]*inv0);
        *(__half2*)(og1 + d) = __floats2half2_rn(o[nt][2]*inv1, o[nt][3]*inv1);
    }
}

// ---------------------------------------------------------------------------
extern "C" void kernel_launch(void* const* d_in, const int* in_sizes, int n_in,
                              void* d_out, int out_size) {
    const float* x      = (const float*)d_in[0];
    const float* w_qkv  = (const float*)d_in[1];
    const float* w_proj = (const float*)d_in[2];
    const float* b_proj = (const float*)d_in[3];
    float* out = (float*)d_out;

    cudaFuncSetAttribute(attn_kernel,
                         cudaFuncAttributeMaxDynamicSharedMemorySize, ATTN_SMEM);
    cudaFuncSetAttribute(qkv_gemm,
                         cudaFuncAttributeMaxDynamicSharedMemorySize, GEMM_SMEM);
    cudaFuncSetAttribute(proj_gemm,
                         cudaFuncAttributeMaxDynamicSharedMemorySize, GEMM_SMEM);

    prep_all<<<8192, 256>>>(x, w_qkv, w_proj);
    qkv_gemm<<<dim3(NQKV/128, M_/128), 256, GEMM_SMEM>>>();
    attn_kernel<<<dim3(T_/128, B_*H_), 256, ATTN_SMEM>>>();
    proj_gemm<<<dim3(C_/128, M_/128), 256, GEMM_SMEM>>>(b_proj, out);
}

// round 13
// speedup vs baseline: 2.1339x; 1.0880x over previous
#include <cuda_runtime.h>
#include <cuda_fp16.h>
#include <math.h>

#define B_ 2
#define T_ 2048
#define C_ 1024
#define H_ 16
#define D_ 64
#define M_ (B_*T_)          // 4096
#define NQKV (3*C_)         // 3072

typedef unsigned int u32;

// Scratch (allocation-free rule: __device__ globals), all fp16
__device__ __align__(16) __half g_qh[(size_t)B_*H_*T_*D_];
__device__ __align__(16) __half g_kh[(size_t)B_*H_*T_*D_];
__device__ __align__(16) __half g_vh[(size_t)B_*H_*T_*D_];
__device__ __align__(16) __half g_atth[(size_t)M_*C_];   // [b][t][h][d]
__device__ __align__(16) __half g_xh[(size_t)M_*C_];     // x half        [M][K]
__device__ __align__(16) __half g_wqh[(size_t)C_*NQKV];  // w_qkv half    [K][N]
__device__ __align__(16) __half g_wph[(size_t)C_*C_];    // w_proj half   [K][N]
__device__ u32 g_tc0;                                    // qkv tile counter
__device__ u32 g_tc1;                                    // attn item counter

// ---------------------------------------------------------------------------
// Primitives
// ---------------------------------------------------------------------------
__device__ __forceinline__ void mma_f16(float c[4], u32 a0, u32 a1, u32 a2, u32 a3,
                                        u32 b0, u32 b1) {
    asm volatile("mma.sync.aligned.m16n8k16.row.col.f32.f16.f16.f32 "
                 "{%0,%1,%2,%3}, {%4,%5,%6,%7}, {%8,%9}, {%0,%1,%2,%3};"
                 : "+f"(c[0]), "+f"(c[1]), "+f"(c[2]), "+f"(c[3])
                 : "r"(a0), "r"(a1), "r"(a2), "r"(a3), "r"(b0), "r"(b1));
}
__device__ __forceinline__ void ldsm4(u32& r0, u32& r1, u32& r2, u32& r3, u32 addr) {
    asm volatile("ldmatrix.sync.aligned.m8n8.x4.shared.b16 {%0,%1,%2,%3}, [%4];"
                 : "=r"(r0), "=r"(r1), "=r"(r2), "=r"(r3) : "r"(addr));
}
__device__ __forceinline__ void ldsm4t(u32& r0, u32& r1, u32& r2, u32& r3, u32 addr) {
    asm volatile("ldmatrix.sync.aligned.m8n8.x4.trans.shared.b16 {%0,%1,%2,%3}, [%4];"
                 : "=r"(r0), "=r"(r1), "=r"(r2), "=r"(r3) : "r"(addr));
}
__device__ __forceinline__ void cp16(void* smem, const void* gmem) {
    u32 s = (u32)__cvta_generic_to_shared(smem);
    asm volatile("cp.async.cg.shared.global [%0], [%1], 16;\n" :: "r"(s), "l"(gmem));
}
__device__ __forceinline__ u32 packh2(float a, float b) {
    __half2 h = __floats2half2_rn(a, b);
    return *reinterpret_cast<u32*>(&h);
}
__device__ __forceinline__ float ex2f(float x) {
    float r; asm("ex2.approx.f32 %0, %1;" : "=f"(r) : "f"(x)); return r;
}

// ---------------------------------------------------------------------------
// Prep: streaming fp32->fp16 converts + work-counter reset.
// Blocks [0,4096): x. [4096,7168): w_qkv. [7168,8192): w_proj.
// ---------------------------------------------------------------------------
__global__ __launch_bounds__(256) void prep_all(const float* __restrict__ x,
                                                const float* __restrict__ wq,
                                                const float* __restrict__ wp) {
    int bid = blockIdx.x, tid = threadIdx.x;
    if (bid == 0 && tid == 0) { g_tc0 = 0; g_tc1 = 0; }
    const float4* src; __half2* dst; int i;
    if (bid < 4096)      { src = (const float4*)x;  dst = (__half2*)g_xh;  i = bid*256 + tid; }
    else if (bid < 7168) { src = (const float4*)wq; dst = (__half2*)g_wqh; i = (bid-4096)*256 + tid; }
    else                 { src = (const float4*)wp; dst = (__half2*)g_wph; i = (bid-7168)*256 + tid; }
    float4 v = src[i];
    dst[i*2+0] = __floats2half2_rn(v.x, v.y);
    dst[i*2+1] = __floats2half2_rn(v.z, v.w);
}

// ---------------------------------------------------------------------------
// fp16 tensor GEMM body: 128x128 tile, BK=64, 256 threads (8 warps 2m x 4n),
// 2-stage cp.async, ONE barrier per k-tile.
// ---------------------------------------------------------------------------
#define ASTR 72                        // halfs, A row stride
#define BSTR 136                       // halfs, B row stride
#define TILE_A (128*ASTR*2)            // 18432
#define TILE_BB (64*BSTR*2)            // 17408
#define STG_B (TILE_A + TILE_BB)       // 35840
#define GEMM_SMEM (2*STG_B)            // 71680
#define NIT (C_/64)                    // 16

struct GemmFrags { float c[4][4][4]; };    // [mt][nt][frag]

template<int NDIM>
__device__ __forceinline__ void gemm_f16_body(const __half* __restrict__ A,
                                              const __half* __restrict__ Bw,
                                              char* smem, int m0, int n0,
                                              GemmFrags& F) {
    int tid = threadIdx.x;
    int lane = tid & 31, wid = tid >> 5;
    int warp_m = wid >> 2, warp_n = wid & 3;    // 2 x 4
    u32 base = (u32)__cvta_generic_to_shared(smem);

    int l8 = lane & 7;
    int arow = l8 + ((lane >> 3) & 1) * 8, ac = (lane >> 4) * 16;

    auto issue = [&](int k0, int s) {
        __half* Ab = (__half*)(smem + s*STG_B);
        __half* Bb = (__half*)(smem + s*STG_B + TILE_A);
        #pragma unroll
        for (int it = 0; it < 4; ++it) {
            int id = it*256 + tid;
            int row = id >> 3, c = (id & 7) * 8;
            cp16(Ab + row*ASTR + c, A + (size_t)(m0 + row)*C_ + k0 + c);
        }
        #pragma unroll
        for (int it = 0; it < 4; ++it) {
            int id = it*256 + tid;
            int krow = id >> 4, c = (id & 15) * 8;
            cp16(Bb + krow*BSTR + c, Bw + (size_t)(k0 + krow)*NDIM + n0 + c);
        }
        asm volatile("cp.async.commit_group;\n");
    };

    issue(0, 0);
    for (int it = 0; it < NIT; ++it) {
        int s = it & 1;
        asm volatile("cp.async.wait_group 0;\n");
        __syncthreads();                          // all warps done with buffer s^1
        if (it + 1 < NIT) issue((it+1)*64, s^1);  // safe: nobody reads s^1 anymore
        u32 Ab = base + s*STG_B;
        u32 Bb = Ab + TILE_A;
        #pragma unroll
        for (int ks = 0; ks < 4; ++ks) {
            int kk = ks*16;
            u32 af[4][4], bf[2][4];
            #pragma unroll
            for (int mt = 0; mt < 4; ++mt)
                ldsm4(af[mt][0], af[mt][1], af[mt][2], af[mt][3],
                      Ab + (warp_m*64 + mt*16 + arow)*144 + kk*2 + ac);
            #pragma unroll
            for (int j = 0; j < 2; ++j)
                ldsm4t(bf[j][0], bf[j][1], bf[j][2], bf[j][3],
                       Bb + (kk + arow)*272 + (warp_n*32 + j*16)*2 + ac);
            #pragma unroll
            for (int mt = 0; mt < 4; ++mt)
                #pragma unroll
                for (int nt = 0; nt < 4; ++nt)
                    mma_f16(F.c[mt][nt], af[mt][0], af[mt][1], af[mt][2], af[mt][3],
                            bf[nt>>1][(nt&1)*2], bf[nt>>1][(nt&1)*2+1]);
        }
    }
}

// Persistent qkv: 296 CTAs pull tiles [0,768) via atomic counter.
__global__ __launch_bounds__(256, 2) void qkv_gemm() {
    extern __shared__ char smg[];
    __shared__ u32 s_tile;
    int tid = threadIdx.x;
    int lane = tid & 31, wid = tid >> 5;
    int warp_m = wid >> 2, warp_n = wid & 3;
    int lr = lane >> 2, lc = lane & 3;

    for (;;) {
        if (tid == 0) s_tile = atomicAdd(&g_tc0, 1u);
        __syncthreads();                // also guards smem reuse across tiles
        u32 tile = s_tile;
        if (tile >= 768u) return;
        int m0 = (int)(tile & 31) * 128;
        int n0 = (int)(tile >> 5) * 128;

        GemmFrags F = {};
        gemm_f16_body<NQKV>(g_xh, g_wqh, smg, m0, n0, F);

        #pragma unroll
        for (int mt = 0; mt < 4; ++mt) {
            #pragma unroll
            for (int nt = 0; nt < 4; ++nt) {
                #pragma unroll
                for (int f = 0; f < 4; ++f) {
                    int m = m0 + warp_m*64 + mt*16 + lr + (f >> 1)*8;
                    int n = n0 + warp_n*32 + nt*8 + lc*2 + (f & 1);
                    int bb = m >> 11, t = m & 2047;
                    int three = n % 3;
                    int hd = n / 3;
                    int h = hd >> 6, d = hd & 63;
                    size_t dst = (((size_t)(bb*H_ + h))*T_ + t)*D_ + d;
                    __half v = __float2half_rn(F.c[mt][nt][f]);
                    if (three == 0)      g_qh[dst] = v;
                    else if (three == 1) g_kh[dst] = v;
                    else                 g_vh[dst] = v;
                }
            }
        }
    }
}

__global__ __launch_bounds__(256, 2) void proj_gemm(const float* __restrict__ bias,
                                                    float* __restrict__ out) {
    extern __shared__ char smg[];
    int tid = threadIdx.x;
    int lane = tid & 31, wid = tid >> 5;
    int warp_m = wid >> 2, warp_n = wid & 3;
    int lr = lane >> 2, lc = lane & 3;
    int m0 = blockIdx.y * 128, n0 = blockIdx.x * 128;

    GemmFrags F = {};
    gemm_f16_body<C_>(g_atth, g_wph, smg, m0, n0, F);

    #pragma unroll
    for (int mt = 0; mt < 4; ++mt) {
        #pragma unroll
        for (int nt = 0; nt < 4; ++nt) {
            #pragma unroll
            for (int f = 0; f < 4; ++f) {
                int m = m0 + warp_m*64 + mt*16 + lr + (f >> 1)*8;
                int n = n0 + warp_n*32 + nt*8 + lc*2 + (f & 1);
                out[(size_t)m * C_ + n] = F.c[mt][nt][f] + bias[n];
            }
        }
    }
}

// ---------------------------------------------------------------------------
// Flash attention, FA-2 register style, persistent CTAs with heavy-first
// work stealing. Item idx -> qt = 15 - idx/32 (heavy first), bh = idx & 31.
// ---------------------------------------------------------------------------
#define AHST 72
#define AQO 0
#define AKO (AQO + 128*AHST*2)          // 18432
#define AVO (AKO + 2*64*AHST*2)         // 36864
#define ATTN_SMEM (AVO + 2*64*AHST*2)   // 55296

__global__ __launch_bounds__(256, 2) void attn_kernel() {
    extern __shared__ char smc[];
    __shared__ u32 s_item;
    __half* Qs = (__half*)(smc + AQO);
    __half* Kb = (__half*)(smc + AKO);
    __half* Vb = (__half*)(smc + AVO);
    u32 base = (u32)__cvta_generic_to_shared(smc);

    int tid = threadIdx.x;
    int lane = tid & 31, wid = tid >> 5;
    int lr = lane >> 2, lc = lane & 3;
    int l8 = lane & 7;
    int arow = l8 + ((lane >> 3) & 1) * 8, ac = (lane >> 4) * 16;
    int brow = l8 + (lane >> 4) * 8,       bc = ((lane >> 3) & 1) * 16;
    const float scale2 = 0.125f * 1.4426950408889634f;   // scale * log2(e)

    for (;;) {
        if (tid == 0) s_item = atomicAdd(&g_tc1, 1u);
        __syncthreads();                // also guards smem reuse across items
        u32 item = s_item;
        if (item >= 512u) return;
        int qt = 15 - (int)(item >> 5);           // heavy items first
        int bh = (int)(item & 31);
        int b = bh >> 4, h = bh & 15;
        int qBase = qt * 128;
        int rbase = qBase + wid*16;

        const __half* qg  = g_qh + (((size_t)(b*H_ + h))*T_ + qBase)*D_;
        const __half* kgb = g_kh + ((size_t)(b*H_ + h))*T_*D_;
        const __half* vgb = g_vh + ((size_t)(b*H_ + h))*T_*D_;

        auto issueKV = [&](int kt, int s) {
            const __half* kg = kgb + (size_t)kt*64*D_;
            const __half* vg = vgb + (size_t)kt*64*D_;
            __half* Kd = Kb + s*64*AHST;
            __half* Vd = Vb + s*64*AHST;
            #pragma unroll
            for (int it = 0; it < 2; ++it) {
                int id = it*256 + tid;
                int row = id >> 3, c = (id & 7) * 8;
                cp16(Kd + row*AHST + c, kg + (size_t)row*D_ + c);
                cp16(Vd + row*AHST + c, vg + (size_t)row*D_ + c);
            }
            asm volatile("cp.async.commit_group;\n");
        };

        #pragma unroll
        for (int it = 0; it < 4; ++it) {
            int id = it*256 + tid;
            int row = id >> 3, c = (id & 7) * 8;
            cp16(Qs + row*AHST + c, qg + (size_t)row*D_ + c);
        }
        issueKV(0, 0);

        u32 qf[4][4];
        float o[8][4] = {};
        float m0v = -INFINITY, m1v = -INFINITY, l0v = 0.0f, l1v = 0.0f;
        int nkt = 2*qt + 2;

        for (int kt = 0; kt < nkt; ++kt) {
            int s = kt & 1;
            asm volatile("cp.async.wait_group 0;\n");
            __syncthreads();
            if (kt + 1 < nkt) issueKV(kt+1, s^1);
            if (kt == 0) {
                #pragma unroll
                for (int ks = 0; ks < 4; ++ks)
                    ldsm4(qf[ks][0], qf[ks][1], qf[ks][2], qf[ks][3],
                          base + AQO + (wid*16 + arow)*144 + ks*32 + ac);
            }
            u32 Ksm = base + AKO + s*64*AHST*2;
            u32 Vsm = base + AVO + s*64*AHST*2;
            int kBase = kt * 64;

            // Phase A: S = Q K^T
            float s8[8][4] = {};
            #pragma unroll
            for (int ks = 0; ks < 4; ++ks) {
                int kb = ks*32;
                u32 bf[4][4];
                #pragma unroll
                for (int j = 0; j < 4; ++j)
                    ldsm4(bf[j][0], bf[j][1], bf[j][2], bf[j][3],
                          Ksm + (j*16 + brow)*144 + kb + bc);
                #pragma unroll
                for (int nt = 0; nt < 8; ++nt)
                    mma_f16(s8[nt], qf[ks][0], qf[ks][1], qf[ks][2], qf[ks][3],
                            bf[nt>>1][(nt&1)*2], bf[nt>>1][(nt&1)*2+1]);
            }

            // Scale (base-2) + causal mask
            bool need_mask = (kBase + 63 > rbase);
            if (need_mask) {
                #pragma unroll
                for (int nt = 0; nt < 8; ++nt)
                    #pragma unroll
                    for (int f = 0; f < 4; ++f) {
                        int row = rbase + lr + (f >> 1)*8;
                        int col = kBase + nt*8 + lc*2 + (f & 1);
                        s8[nt][f] = (col <= row) ? s8[nt][f]*scale2 : -INFINITY;
                    }
            } else {
                #pragma unroll
                for (int nt = 0; nt < 8; ++nt)
                    #pragma unroll
                    for (int f = 0; f < 4; ++f) s8[nt][f] *= scale2;
            }

            // Register softmax (base-2, quad shuffles)
            float lm0 = -INFINITY, lm1 = -INFINITY;
            #pragma unroll
            for (int nt = 0; nt < 8; ++nt) {
                lm0 = fmaxf(lm0, fmaxf(s8[nt][0], s8[nt][1]));
                lm1 = fmaxf(lm1, fmaxf(s8[nt][2], s8[nt][3]));
            }
            lm0 = fmaxf(lm0, __shfl_xor_sync(0xffffffffu, lm0, 1));
            lm0 = fmaxf(lm0, __shfl_xor_sync(0xffffffffu, lm0, 2));
            lm1 = fmaxf(lm1, __shfl_xor_sync(0xffffffffu, lm1, 1));
            lm1 = fmaxf(lm1, __shfl_xor_sync(0xffffffffu, lm1, 2));
            float nm0 = fmaxf(m0v, lm0), nm1 = fmaxf(m1v, lm1);
            float r0 = ex2f(m0v - nm0), r1 = ex2f(m1v - nm1);
            float ls0 = 0.0f, ls1 = 0.0f;
            #pragma unroll
            for (int nt = 0; nt < 8; ++nt) {
                s8[nt][0] = ex2f(s8[nt][0] - nm0); ls0 += s8[nt][0];
                s8[nt][1] = ex2f(s8[nt][1] - nm0); ls0 += s8[nt][1];
                s8[nt][2] = ex2f(s8[nt][2] - nm1); ls1 += s8[nt][2];
                s8[nt][3] = ex2f(s8[nt][3] - nm1); ls1 += s8[nt][3];
            }
            ls0 += __shfl_xor_sync(0xffffffffu, ls0, 1);
            ls0 += __shfl_xor_sync(0xffffffffu, ls0, 2);
            ls1 += __shfl_xor_sync(0xffffffffu, ls1, 1);
            ls1 += __shfl_xor_sync(0xffffffffu, ls1, 2);
            l0v = l0v*r0 + ls0; m0v = nm0;
            l1v = l1v*r1 + ls1; m1v = nm1;
            #pragma unroll
            for (int nt = 0; nt < 8; ++nt) {
                o[nt][0] *= r0; o[nt][1] *= r0;
                o[nt][2] *= r1; o[nt][3] *= r1;
            }

            // P fragments directly from S fragments
            u32 pf[4][4];
            #pragma unroll
            for (int ks = 0; ks < 4; ++ks) {
                pf[ks][0] = packh2(s8[2*ks  ][0], s8[2*ks  ][1]);
                pf[ks][1] = packh2(s8[2*ks  ][2], s8[2*ks  ][3]);
                pf[ks][2] = packh2(s8[2*ks+1][0], s8[2*ks+1][1]);
                pf[ks][3] = packh2(s8[2*ks+1][2], s8[2*ks+1][3]);
            }

            // Phase C: O += P V
            #pragma unroll
            for (int ks = 0; ks < 4; ++ks) {
                int kk = ks*16;
                u32 vf[4][4];
                #pragma unroll
                for (int j = 0; j < 4; ++j)
                    ldsm4t(vf[j][0], vf[j][1], vf[j][2], vf[j][3],
                           Vsm + (kk + arow)*144 + (j*16)*2 + ac);
                #pragma unroll
                for (int nt = 0; nt < 8; ++nt)
                    mma_f16(o[nt], pf[ks][0], pf[ks][1], pf[ks][2], pf[ks][3],
                            vf[nt>>1][(nt&1)*2], vf[nt>>1][(nt&1)*2+1]);
            }
        }

        // Epilogue
        float inv0 = 1.0f / l0v, inv1 = 1.0f / l1v;
        int t0 = rbase + lr, t1 = t0 + 8;
        __half* og0 = g_atth + (((size_t)(b*T_ + t0))*H_ + h)*D_;
        __half* og1 = g_atth + (((size_t)(b*T_ + t1))*H_ + h)*D_;
        #pragma unroll
        for (int nt = 0; nt < 8; ++nt) {
            int d = nt*8 + lc*2;
            *(__half2*)(og0 + d) = __floats2half2_rn(o[nt][0]*inv0, o[nt][1]*inv0);
            *(__half2*)(og1 + d) = __floats2half2_rn(o[nt][2]*inv1, o[nt][3]*inv1);
        }
    }
}

// ---------------------------------------------------------------------------
extern "C" void kernel_launch(void* const* d_in, const int* in_sizes, int n_in,
                              void* d_out, int out_size) {
    const float* x      = (const float*)d_in[0];
    const float* w_qkv  = (const float*)d_in[1];
    const float* w_proj = (const float*)d_in[2];
    const float* b_proj = (const float*)d_in[3];
    float* out = (float*)d_out;

    cudaFuncSetAttribute(attn_kernel,
                         cudaFuncAttributeMaxDynamicSharedMemorySize, ATTN_SMEM);
    cudaFuncSetAttribute(qkv_gemm,
                         cudaFuncAttributeMaxDynamicSharedMemorySize, GEMM_SMEM);
    cudaFuncSetAttribute(proj_gemm,
                         cudaFuncAttributeMaxDynamicSharedMemorySize, GEMM_SMEM);

    prep_all<<<8192, 256>>>(x, w_qkv, w_proj);
    qkv_gemm<<<296, 256, GEMM_SMEM>>>();
    attn_kernel<<<296, 256, ATTN_SMEM>>>();
    proj_gemm<<<dim3(C_/128, M_/128), 256, GEMM_SMEM>>>(b_proj, out);
}